// round 1
// baseline (speedup 1.0000x reference)
#include <cuda_runtime.h>
#include <math.h>
#include <stdint.h>

#define EMB   1024
#define NH    16
#define HD    64
#define SEQ   2048
#define BATCH 2
#define MROWS (BATCH*SEQ)     // 4096
#define QKVN  (3*EMB)         // 3072
#define EPS   1.1920929e-07f

// ---- scratch (no allocations allowed) ----
__device__ float g_normed[(size_t)MROWS*EMB];
__device__ float g_qkv[(size_t)MROWS*QKVN];
__device__ float g_attn[(size_t)MROWS*EMB];

// ============================================================
// 1) RMSNorm: one block per row (4096 rows x 1024)
// ============================================================
__global__ __launch_bounds__(256) void rmsnorm_kernel(
    const float* __restrict__ x, const float* __restrict__ w,
    float* __restrict__ out)
{
    int row = blockIdx.x;
    int tid = threadIdx.x;
    const float4* xr = (const float4*)(x + (size_t)row*EMB);
    float4 v = xr[tid];
    float ss = v.x*v.x + v.y*v.y + v.z*v.z + v.w*v.w;
    #pragma unroll
    for (int o = 16; o > 0; o >>= 1) ss += __shfl_xor_sync(0xffffffffu, ss, o);
    __shared__ float wsum[8];
    if ((tid & 31) == 0) wsum[tid >> 5] = ss;
    __syncthreads();
    if (tid < 8) {
        float t = wsum[tid];
        #pragma unroll
        for (int o = 4; o > 0; o >>= 1) t += __shfl_xor_sync(0xffu, t, o);
        if (tid == 0) wsum[0] = t;
    }
    __syncthreads();
    float inv = rsqrtf(wsum[0] * (1.0f/EMB) + EPS);
    float4 wv = ((const float4*)w)[tid];
    float4 o4;
    o4.x = v.x*inv*wv.x; o4.y = v.y*inv*wv.y;
    o4.z = v.z*inv*wv.z; o4.w = v.w*inv*wv.w;
    ((float4*)(out + (size_t)row*EMB))[tid] = o4;
}

// ============================================================
// 2) Tiled SGEMM: C[M,N] = A[M,K] @ B[N,K]^T (+ Res)
//    128x128x16 tile, 256 threads, 8x8 micro-tile (split-4)
// ============================================================
__global__ __launch_bounds__(256) void gemm_kn_kernel(
    const float* __restrict__ A, const float* __restrict__ Bm,
    const float* __restrict__ Res, float* __restrict__ C,
    int N, int K)
{
    __shared__ float As[16*132];
    __shared__ float Bs[16*132];
    int tid = threadIdx.x;
    int m0 = blockIdx.y * 128;
    int n0 = blockIdx.x * 128;
    int tx = tid & 15, ty = tid >> 4;

    float acc[8][8];
    #pragma unroll
    for (int i = 0; i < 8; i++)
        #pragma unroll
        for (int j = 0; j < 8; j++) acc[i][j] = 0.0f;

    for (int k0 = 0; k0 < K; k0 += 16) {
        #pragma unroll
        for (int t = 0; t < 2; t++) {
            int task = tid + t*256;          // 512 float4 tasks
            int row = task >> 2, k4 = task & 3;
            float4 a = *(const float4*)(A  + (size_t)(m0+row)*K + k0 + k4*4);
            float4 b = *(const float4*)(Bm + (size_t)(n0+row)*K + k0 + k4*4);
            As[(k4*4+0)*132 + row] = a.x;
            As[(k4*4+1)*132 + row] = a.y;
            As[(k4*4+2)*132 + row] = a.z;
            As[(k4*4+3)*132 + row] = a.w;
            Bs[(k4*4+0)*132 + row] = b.x;
            Bs[(k4*4+1)*132 + row] = b.y;
            Bs[(k4*4+2)*132 + row] = b.z;
            Bs[(k4*4+3)*132 + row] = b.w;
        }
        __syncthreads();
        #pragma unroll
        for (int kk = 0; kk < 16; kk++) {
            float4 a0 = *(float4*)&As[kk*132 + ty*4];
            float4 a1 = *(float4*)&As[kk*132 + 64 + ty*4];
            float4 b0 = *(float4*)&Bs[kk*132 + tx*4];
            float4 b1 = *(float4*)&Bs[kk*132 + 64 + tx*4];
            float ar[8] = {a0.x,a0.y,a0.z,a0.w, a1.x,a1.y,a1.z,a1.w};
            float br[8] = {b0.x,b0.y,b0.z,b0.w, b1.x,b1.y,b1.z,b1.w};
            #pragma unroll
            for (int i = 0; i < 8; i++)
                #pragma unroll
                for (int j = 0; j < 8; j++)
                    acc[i][j] = fmaf(ar[i], br[j], acc[i][j]);
        }
        __syncthreads();
    }

    #pragma unroll
    for (int i = 0; i < 8; i++) {
        int r = m0 + ((i < 4) ? (ty*4 + i) : (64 + ty*4 + i - 4));
        #pragma unroll
        for (int jj = 0; jj < 2; jj++) {
            int c = n0 + jj*64 + tx*4;
            float4 o;
            o.x = acc[i][jj*4+0]; o.y = acc[i][jj*4+1];
            o.z = acc[i][jj*4+2]; o.w = acc[i][jj*4+3];
            if (Res) {
                float4 rv = *(const float4*)(Res + (size_t)r*N + c);
                o.x += rv.x; o.y += rv.y; o.z += rv.z; o.w += rv.w;
            }
            *(float4*)(C + (size_t)r*N + c) = o;
        }
    }
}

// ============================================================
// 3) RoPE in-place on q,k parts of qkv
//    rotated[d] = cos[d]*x[d] + sin[d]*x[(d+32)%64]
// ============================================================
__global__ __launch_bounds__(256) void rope_kernel(
    float* __restrict__ qkv, const float* __restrict__ cosb,
    const float* __restrict__ sinb)
{
    int idx = blockIdx.x * blockDim.x + threadIdx.x; // 2*4096*16*32 = 2^22
    int d  = idx & 31;
    int h  = (idx >> 5) & 15;
    int m  = (idx >> 9) & 4095;
    int t  = idx >> 21;           // 0 = q, 1 = k
    int s  = m & (SEQ - 1);
    float* p = qkv + (size_t)m*QKVN + t*EMB + h*HD;
    float x0 = p[d], x1 = p[d + 32];
    float c0 = cosb[s*HD + d],      c1 = cosb[s*HD + d + 32];
    float s0 = sinb[s*HD + d],      s1 = sinb[s*HD + d + 32];
    p[d]      = c0*x0 + s0*x1;   // swapped[d]   = x[d+32]
    p[d + 32] = c1*x1 + s1*x0;   // swapped[d+32]= x[d]
}

// ============================================================
// 4) Causal flash attention, fp32
//    block = (b, h, 64-row q tile); 256 threads
//    thread (qr = tid>>2, c4 = tid&3) owns q row qr and the
//    interleaved columns/dims {c4 + 4j : j=0..15}
// ============================================================
__global__ __launch_bounds__(256, 2) void flash_kernel(
    const float* __restrict__ qkv, float* __restrict__ attn_out)
{
    __shared__ float k_s[64*65];   // k tile; reused as p tile
    __shared__ float v_s[64*65];

    int qt = blockIdx.x, h = blockIdx.y, b = blockIdx.z;
    int tid = threadIdx.x;
    int qr = tid >> 2, c4 = tid & 3;
    int qm0 = b*SEQ + qt*64;

    // stage q tile into k_s (coalesced), then into registers (scale folded)
    const float* qbase = qkv + (size_t)qm0*QKVN + h*HD;
    for (int i = tid; i < 64*16; i += 256) {
        int row = i >> 4, d4 = i & 15;
        float4 v = *(const float4*)(qbase + (size_t)row*QKVN + d4*4);
        k_s[row*65 + d4*4+0] = v.x;
        k_s[row*65 + d4*4+1] = v.y;
        k_s[row*65 + d4*4+2] = v.z;
        k_s[row*65 + d4*4+3] = v.w;
    }
    __syncthreads();
    float q_r[64];
    #pragma unroll
    for (int d = 0; d < 64; d++) q_r[d] = k_s[qr*65 + d] * 0.125f;

    float m_i = -INFINITY, l_i = 0.0f;
    float o_r[16];
    #pragma unroll
    for (int j = 0; j < 16; j++) o_r[j] = 0.0f;

    const float* kbase = qkv + (size_t)b*SEQ*QKVN + EMB   + h*HD;
    const float* vbase = qkv + (size_t)b*SEQ*QKVN + 2*EMB + h*HD;

    for (int kt = 0; kt <= qt; kt++) {
        __syncthreads();   // previous iter (or q staging) done with smem
        int km0 = kt*64;
        for (int i = tid; i < 64*16; i += 256) {
            int row = i >> 4, d4 = i & 15;
            float4 kv = *(const float4*)(kbase + (size_t)(km0+row)*QKVN + d4*4);
            float4 vv = *(const float4*)(vbase + (size_t)(km0+row)*QKVN + d4*4);
            k_s[row*65 + d4*4+0] = kv.x; k_s[row*65 + d4*4+1] = kv.y;
            k_s[row*65 + d4*4+2] = kv.z; k_s[row*65 + d4*4+3] = kv.w;
            v_s[row*65 + d4*4+0] = vv.x; v_s[row*65 + d4*4+1] = vv.y;
            v_s[row*65 + d4*4+2] = vv.z; v_s[row*65 + d4*4+3] = vv.w;
        }
        __syncthreads();

        // scores for owned columns
        float sj[16];
        bool diag = (kt == qt);
        #pragma unroll
        for (int j = 0; j < 16; j++) {
            int col = c4 + 4*j;
            float a = 0.0f;
            #pragma unroll
            for (int d = 0; d < 64; d++)
                a = fmaf(q_r[d], k_s[col*65 + d], a);
            if (diag && col > qr) a = -INFINITY;
            sj[j] = a;
        }

        // row-wise online softmax (reduce over the 4 lanes of a row)
        float mt = sj[0];
        #pragma unroll
        for (int j = 1; j < 16; j++) mt = fmaxf(mt, sj[j]);
        mt = fmaxf(mt, __shfl_xor_sync(0xffffffffu, mt, 1));
        mt = fmaxf(mt, __shfl_xor_sync(0xffffffffu, mt, 2));
        float m_new = fmaxf(m_i, mt);
        float lsum = 0.0f;
        #pragma unroll
        for (int j = 0; j < 16; j++) {
            sj[j] = __expf(sj[j] - m_new);
            lsum += sj[j];
        }
        lsum += __shfl_xor_sync(0xffffffffu, lsum, 1);
        lsum += __shfl_xor_sync(0xffffffffu, lsum, 2);
        float corr = __expf(m_i - m_new);   // 0 on first iter (m_i = -inf)
        l_i = l_i * corr + lsum;
        m_i = m_new;
        #pragma unroll
        for (int j = 0; j < 16; j++) o_r[j] *= corr;

        __syncthreads();   // everyone done reading k_s
        #pragma unroll
        for (int j = 0; j < 16; j++)
            k_s[qr*65 + (c4 + 4*j)] = sj[j];   // p tile
        __syncthreads();

        // o += p @ v  (thread accumulates its 16 owned dims)
        #pragma unroll 8
        for (int col = 0; col < 64; col++) {
            float p = k_s[qr*65 + col];
            #pragma unroll
            for (int j = 0; j < 16; j++)
                o_r[j] = fmaf(p, v_s[col*65 + c4 + 4*j], o_r[j]);
        }
    }

    float inv_l = 1.0f / l_i;
    float* ob = attn_out + (size_t)(qm0 + qr)*EMB + h*HD;
    #pragma unroll
    for (int j = 0; j < 16; j++)
        ob[c4 + 4*j] = o_r[j] * inv_l;
}

// ============================================================
// launch
// ============================================================
extern "C" void kernel_launch(void* const* d_in, const int* in_sizes, int n_in,
                              void* d_out, int out_size)
{
    const float* emb  = (const float*)d_in[0];
    const float* cosb = (const float*)d_in[1];
    const float* sinb = (const float*)d_in[2];
    const float* nw   = (const float*)d_in[3];
    const float* qkvw = (const float*)d_in[4];
    const float* ow   = (const float*)d_in[5];
    float* out = (float*)d_out;

    float *normed, *qkv, *attn;
    cudaGetSymbolAddress((void**)&normed, g_normed);
    cudaGetSymbolAddress((void**)&qkv,    g_qkv);
    cudaGetSymbolAddress((void**)&attn,   g_attn);

    // 1) RMSNorm
    rmsnorm_kernel<<<MROWS, 256>>>(emb, nw, normed);
    // 2) QKV projection: [4096,1024] @ [3072,1024]^T -> [4096,3072]
    gemm_kn_kernel<<<dim3(QKVN/128, MROWS/128), 256>>>(normed, qkvw, nullptr, qkv, QKVN, EMB);
    // 3) RoPE on q and k
    rope_kernel<<<(2*MROWS*NH*32)/256, 256>>>(qkv, cosb, sinb);
    // 4) causal attention
    flash_kernel<<<dim3(SEQ/64, NH, BATCH), 256>>>(qkv, attn);
    // 5) out projection + residual: [4096,1024] @ [1024,1024]^T + emb
    gemm_kn_kernel<<<dim3(EMB/128, MROWS/128), 256>>>(attn, ow, emb, out, EMB, EMB);
}

// round 2
// speedup vs baseline: 1.0389x; 1.0389x over previous
#include <cuda_runtime.h>
#include <math.h>
#include <stdint.h>

#define EMB   1024
#define NH    16
#define HD    64
#define SEQ   2048
#define BATCH 2
#define MROWS (BATCH*SEQ)     // 4096
#define QKVN  (3*EMB)         // 3072
#define EPS   1.1920929e-07f
#define KPAD  68              // smem row stride in floats (16B aligned, bank-spread)

// ---- scratch (no allocations allowed) ----
__device__ float g_normed[(size_t)MROWS*EMB];
__device__ float g_qkv[(size_t)MROWS*QKVN];
__device__ float g_attn[(size_t)MROWS*EMB];

// ============================================================
// 1) RMSNorm: one block per row (4096 rows x 1024)
// ============================================================
__global__ __launch_bounds__(256) void rmsnorm_kernel(
    const float* __restrict__ x, const float* __restrict__ w,
    float* __restrict__ out)
{
    int row = blockIdx.x;
    int tid = threadIdx.x;
    const float4* xr = (const float4*)(x + (size_t)row*EMB);
    float4 v = xr[tid];
    float ss = v.x*v.x + v.y*v.y + v.z*v.z + v.w*v.w;
    #pragma unroll
    for (int o = 16; o > 0; o >>= 1) ss += __shfl_xor_sync(0xffffffffu, ss, o);
    __shared__ float wsum[8];
    if ((tid & 31) == 0) wsum[tid >> 5] = ss;
    __syncthreads();
    if (tid < 8) {
        float t = wsum[tid];
        #pragma unroll
        for (int o = 4; o > 0; o >>= 1) t += __shfl_xor_sync(0xffu, t, o);
        if (tid == 0) wsum[0] = t;
    }
    __syncthreads();
    float inv = rsqrtf(wsum[0] * (1.0f/EMB) + EPS);
    float4 wv = ((const float4*)w)[tid];
    float4 o4;
    o4.x = v.x*inv*wv.x; o4.y = v.y*inv*wv.y;
    o4.z = v.z*inv*wv.z; o4.w = v.w*inv*wv.w;
    ((float4*)(out + (size_t)row*EMB))[tid] = o4;
}

// ============================================================
// 2) Tiled SGEMM: C[M,N] = A[M,K] @ B[N,K]^T (+ Res)
//    128x128x16 tile, 256 threads, 8x8 micro-tile (split-4)
// ============================================================
__global__ __launch_bounds__(256) void gemm_kn_kernel(
    const float* __restrict__ A, const float* __restrict__ Bm,
    const float* __restrict__ Res, float* __restrict__ C,
    int N, int K)
{
    __shared__ float As[16*132];
    __shared__ float Bs[16*132];
    int tid = threadIdx.x;
    int m0 = blockIdx.y * 128;
    int n0 = blockIdx.x * 128;
    int tx = tid & 15, ty = tid >> 4;

    float acc[8][8];
    #pragma unroll
    for (int i = 0; i < 8; i++)
        #pragma unroll
        for (int j = 0; j < 8; j++) acc[i][j] = 0.0f;

    for (int k0 = 0; k0 < K; k0 += 16) {
        #pragma unroll
        for (int t = 0; t < 2; t++) {
            int task = tid + t*256;          // 512 float4 tasks
            int row = task >> 2, k4 = task & 3;
            float4 a = *(const float4*)(A  + (size_t)(m0+row)*K + k0 + k4*4);
            float4 b = *(const float4*)(Bm + (size_t)(n0+row)*K + k0 + k4*4);
            As[(k4*4+0)*132 + row] = a.x;
            As[(k4*4+1)*132 + row] = a.y;
            As[(k4*4+2)*132 + row] = a.z;
            As[(k4*4+3)*132 + row] = a.w;
            Bs[(k4*4+0)*132 + row] = b.x;
            Bs[(k4*4+1)*132 + row] = b.y;
            Bs[(k4*4+2)*132 + row] = b.z;
            Bs[(k4*4+3)*132 + row] = b.w;
        }
        __syncthreads();
        #pragma unroll
        for (int kk = 0; kk < 16; kk++) {
            float4 a0 = *(float4*)&As[kk*132 + ty*4];
            float4 a1 = *(float4*)&As[kk*132 + 64 + ty*4];
            float4 b0 = *(float4*)&Bs[kk*132 + tx*4];
            float4 b1 = *(float4*)&Bs[kk*132 + 64 + tx*4];
            float ar[8] = {a0.x,a0.y,a0.z,a0.w, a1.x,a1.y,a1.z,a1.w};
            float br[8] = {b0.x,b0.y,b0.z,b0.w, b1.x,b1.y,b1.z,b1.w};
            #pragma unroll
            for (int i = 0; i < 8; i++)
                #pragma unroll
                for (int j = 0; j < 8; j++)
                    acc[i][j] = fmaf(ar[i], br[j], acc[i][j]);
        }
        __syncthreads();
    }

    #pragma unroll
    for (int i = 0; i < 8; i++) {
        int r = m0 + ((i < 4) ? (ty*4 + i) : (64 + ty*4 + i - 4));
        #pragma unroll
        for (int jj = 0; jj < 2; jj++) {
            int c = n0 + jj*64 + tx*4;
            float4 o;
            o.x = acc[i][jj*4+0]; o.y = acc[i][jj*4+1];
            o.z = acc[i][jj*4+2]; o.w = acc[i][jj*4+3];
            if (Res) {
                float4 rv = *(const float4*)(Res + (size_t)r*N + c);
                o.x += rv.x; o.y += rv.y; o.z += rv.z; o.w += rv.w;
            }
            *(float4*)(C + (size_t)r*N + c) = o;
        }
    }
}

// ============================================================
// 3) RoPE in-place on q,k parts of qkv
// ============================================================
__global__ __launch_bounds__(256) void rope_kernel(
    float* __restrict__ qkv, const float* __restrict__ cosb,
    const float* __restrict__ sinb)
{
    int idx = blockIdx.x * blockDim.x + threadIdx.x; // 2*4096*16*32 = 2^22
    int d  = idx & 31;
    int h  = (idx >> 5) & 15;
    int m  = (idx >> 9) & 4095;
    int t  = idx >> 21;           // 0 = q, 1 = k
    int s  = m & (SEQ - 1);
    float* p = qkv + (size_t)m*QKVN + t*EMB + h*HD;
    float x0 = p[d], x1 = p[d + 32];
    float c0 = cosb[s*HD + d],      c1 = cosb[s*HD + d + 32];
    float s0 = sinb[s*HD + d],      s1 = sinb[s*HD + d + 32];
    p[d]      = c0*x0 + s0*x1;
    p[d + 32] = c1*x1 + s1*x0;
}

// ============================================================
// 4) Causal flash attention, fp32, vectorized smem (LDS.128)
//    block = (b, h, 64-row q tile); 256 threads
//    thread (qr = tid>>2, c4 = tid&3):
//      scores : owns cols {c4 + 4j, j=0..15}
//      PV/out : owns dims {jj*16 + c4*4 + 0..3, jj=0..3}
// ============================================================
__global__ __launch_bounds__(256, 2) void flash_kernel(
    const float* __restrict__ qkv, float* __restrict__ attn_out)
{
    __shared__ float k_s[64*KPAD];   // k tile; reused for q staging + p tile
    __shared__ float v_s[64*KPAD];

    int qt = blockIdx.x, h = blockIdx.y, b = blockIdx.z;
    int tid = threadIdx.x;
    int qr = tid >> 2, c4 = tid & 3;
    int qm0 = b*SEQ + qt*64;

    // stage q tile (coalesced), then into registers (scale folded)
    const float* qbase = qkv + (size_t)qm0*QKVN + h*HD;
    for (int i = tid; i < 64*16; i += 256) {
        int row = i >> 4, d4 = i & 15;
        float4 v = *(const float4*)(qbase + (size_t)row*QKVN + d4*4);
        *(float4*)&k_s[row*KPAD + d4*4] = v;
    }
    __syncthreads();
    float4 q4[16];
    #pragma unroll
    for (int d4 = 0; d4 < 16; d4++) {
        float4 t = *(float4*)&k_s[qr*KPAD + d4*4];
        q4[d4].x = t.x*0.125f; q4[d4].y = t.y*0.125f;
        q4[d4].z = t.z*0.125f; q4[d4].w = t.w*0.125f;
    }

    float m_i = -INFINITY, l_i = 0.0f;
    float4 o4[4];
    #pragma unroll
    for (int jj = 0; jj < 4; jj++) o4[jj] = make_float4(0.f,0.f,0.f,0.f);

    const float* kbase = qkv + (size_t)b*SEQ*QKVN + EMB   + h*HD;
    const float* vbase = qkv + (size_t)b*SEQ*QKVN + 2*EMB + h*HD;

    for (int kt = 0; kt <= qt; kt++) {
        __syncthreads();   // previous iter (or q staging) done with smem
        int km0 = kt*64;
        for (int i = tid; i < 64*16; i += 256) {
            int row = i >> 4, d4 = i & 15;
            float4 kv = *(const float4*)(kbase + (size_t)(km0+row)*QKVN + d4*4);
            float4 vv = *(const float4*)(vbase + (size_t)(km0+row)*QKVN + d4*4);
            *(float4*)&k_s[row*KPAD + d4*4] = kv;
            *(float4*)&v_s[row*KPAD + d4*4] = vv;
        }
        __syncthreads();

        // scores for owned columns (float4 smem reads, qr-broadcast)
        float sj[16];
        bool diag = (kt == qt);
        #pragma unroll
        for (int j = 0; j < 16; j++) {
            int col = c4 + 4*j;
            float4 a4 = make_float4(0.f,0.f,0.f,0.f);
            #pragma unroll
            for (int d4 = 0; d4 < 16; d4++) {
                float4 k4 = *(float4*)&k_s[col*KPAD + d4*4];
                a4.x = fmaf(q4[d4].x, k4.x, a4.x);
                a4.y = fmaf(q4[d4].y, k4.y, a4.y);
                a4.z = fmaf(q4[d4].z, k4.z, a4.z);
                a4.w = fmaf(q4[d4].w, k4.w, a4.w);
            }
            float a = (a4.x + a4.y) + (a4.z + a4.w);
            if (diag && col > qr) a = -INFINITY;
            sj[j] = a;
        }

        // row-wise online softmax (reduce over the 4 lanes of a row)
        float mt = sj[0];
        #pragma unroll
        for (int j = 1; j < 16; j++) mt = fmaxf(mt, sj[j]);
        mt = fmaxf(mt, __shfl_xor_sync(0xffffffffu, mt, 1));
        mt = fmaxf(mt, __shfl_xor_sync(0xffffffffu, mt, 2));
        float m_new = fmaxf(m_i, mt);
        float lsum = 0.0f;
        #pragma unroll
        for (int j = 0; j < 16; j++) {
            sj[j] = __expf(sj[j] - m_new);
            lsum += sj[j];
        }
        lsum += __shfl_xor_sync(0xffffffffu, lsum, 1);
        lsum += __shfl_xor_sync(0xffffffffu, lsum, 2);
        float corr = __expf(m_i - m_new);   // 0 on first iter
        l_i = l_i * corr + lsum;
        m_i = m_new;
        #pragma unroll
        for (int jj = 0; jj < 4; jj++) {
            o4[jj].x *= corr; o4[jj].y *= corr;
            o4[jj].z *= corr; o4[jj].w *= corr;
        }

        __syncthreads();   // everyone done reading k_s
        #pragma unroll
        for (int j = 0; j < 16; j++)
            k_s[qr*KPAD + (c4 + 4*j)] = sj[j];   // p tile
        __syncthreads();

        // o += p @ v  (4x LDS.128 per col for 16 FMA)
        #pragma unroll 4
        for (int col = 0; col < 64; col++) {
            float p = k_s[qr*KPAD + col];
            #pragma unroll
            for (int jj = 0; jj < 4; jj++) {
                float4 v4 = *(float4*)&v_s[col*KPAD + jj*16 + c4*4];
                o4[jj].x = fmaf(p, v4.x, o4[jj].x);
                o4[jj].y = fmaf(p, v4.y, o4[jj].y);
                o4[jj].z = fmaf(p, v4.z, o4[jj].z);
                o4[jj].w = fmaf(p, v4.w, o4[jj].w);
            }
        }
    }

    float inv_l = 1.0f / l_i;
    float* ob = attn_out + (size_t)(qm0 + qr)*EMB + h*HD;
    #pragma unroll
    for (int jj = 0; jj < 4; jj++) {
        float4 o;
        o.x = o4[jj].x*inv_l; o.y = o4[jj].y*inv_l;
        o.z = o4[jj].z*inv_l; o.w = o4[jj].w*inv_l;
        *(float4*)(ob + jj*16 + c4*4) = o;
    }
}

// ============================================================
// launch
// ============================================================
extern "C" void kernel_launch(void* const* d_in, const int* in_sizes, int n_in,
                              void* d_out, int out_size)
{
    const float* emb  = (const float*)d_in[0];
    const float* cosb = (const float*)d_in[1];
    const float* sinb = (const float*)d_in[2];
    const float* nw   = (const float*)d_in[3];
    const float* qkvw = (const float*)d_in[4];
    const float* ow   = (const float*)d_in[5];
    float* out = (float*)d_out;

    float *normed, *qkv, *attn;
    cudaGetSymbolAddress((void**)&normed, g_normed);
    cudaGetSymbolAddress((void**)&qkv,    g_qkv);
    cudaGetSymbolAddress((void**)&attn,   g_attn);

    // 1) RMSNorm
    rmsnorm_kernel<<<MROWS, 256>>>(emb, nw, normed);
    // 2) QKV projection: [4096,1024] @ [3072,1024]^T -> [4096,3072]
    gemm_kn_kernel<<<dim3(QKVN/128, MROWS/128), 256>>>(normed, qkvw, nullptr, qkv, QKVN, EMB);
    // 3) RoPE on q and k
    rope_kernel<<<(2*MROWS*NH*32)/256, 256>>>(qkv, cosb, sinb);
    // 4) causal attention
    flash_kernel<<<dim3(SEQ/64, NH, BATCH), 256>>>(qkv, attn);
    // 5) out projection + residual: [4096,1024] @ [1024,1024]^T + emb
    gemm_kn_kernel<<<dim3(EMB/128, MROWS/128), 256>>>(attn, ow, emb, out, EMB, EMB);
}

// round 4
// speedup vs baseline: 1.0919x; 1.0510x over previous
#include <cuda_runtime.h>
#include <math.h>
#include <stdint.h>

#define EMB   1024
#define NH    16
#define HD    64
#define SEQ   2048
#define BATCH 2
#define MROWS (BATCH*SEQ)     // 4096
#define QKVN  (3*EMB)         // 3072
#define EPS   1.1920929e-07f
#define KPAD  68

// ---- scratch (no allocations allowed) ----
__device__ float g_qkv[(size_t)MROWS*QKVN];
__device__ float g_nrm_h[(size_t)MROWS*EMB];
__device__ float g_nrm_l[(size_t)MROWS*EMB];
__device__ float g_att_h[(size_t)MROWS*EMB];
__device__ float g_att_l[(size_t)MROWS*EMB];
__device__ float g_wqkv_h[(size_t)QKVN*EMB];
__device__ float g_wqkv_l[(size_t)QKVN*EMB];
__device__ float g_wo_h[(size_t)EMB*EMB];
__device__ float g_wo_l[(size_t)EMB*EMB];

// ============================================================
// helpers
// ============================================================
__device__ __forceinline__ uint32_t smem_u32(const void* p) {
    uint32_t a;
    asm("{ .reg .u64 t; cvta.to.shared.u64 t, %1; cvt.u32.u64 %0, t; }" : "=r"(a) : "l"(p));
    return a;
}
__device__ __forceinline__ uint32_t f2tf32(float x) {
    uint32_t r; asm("cvt.rna.tf32.f32 %0, %1;" : "=r"(r) : "f"(x)); return r;
}
__device__ __forceinline__ void split_tf32(float x, float& hi, float& lo) {
    uint32_t h = f2tf32(x);
    hi = __uint_as_float(h);
    lo = __uint_as_float(f2tf32(x - hi));
}
__device__ __forceinline__ void mma_tf32(float* c, const uint32_t* a,
                                         uint32_t b0, uint32_t b1) {
    asm volatile(
        "mma.sync.aligned.m16n8k8.row.col.f32.tf32.tf32.f32 "
        "{%0,%1,%2,%3}, {%4,%5,%6,%7}, {%8,%9}, {%0,%1,%2,%3};"
        : "+f"(c[0]), "+f"(c[1]), "+f"(c[2]), "+f"(c[3])
        : "r"(a[0]), "r"(a[1]), "r"(a[2]), "r"(a[3]), "r"(b0), "r"(b1));
}
__device__ __forceinline__ void cp16(uint32_t sdst, const void* gsrc) {
    asm volatile("cp.async.cg.shared.global [%0], [%1], 16;" :: "r"(sdst), "l"(gsrc));
}
#define CP_COMMIT() asm volatile("cp.async.commit_group;")
#define CP_WAIT1()  asm volatile("cp.async.wait_group 1;")
#define CP_WAIT0()  asm volatile("cp.async.wait_group 0;")

// ============================================================
// tf32 hi/lo split of a weight matrix (elementwise, float4)
// ============================================================
__global__ __launch_bounds__(256) void conv_tf32_kernel(
    const float* __restrict__ x, float* __restrict__ hi, float* __restrict__ lo)
{
    int i = blockIdx.x * 256 + threadIdx.x;
    float4 v = ((const float4*)x)[i];
    float4 h4, l4;
    split_tf32(v.x, h4.x, l4.x);
    split_tf32(v.y, h4.y, l4.y);
    split_tf32(v.z, h4.z, l4.z);
    split_tf32(v.w, h4.w, l4.w);
    ((float4*)hi)[i] = h4;
    ((float4*)lo)[i] = l4;
}

// ============================================================
// GEMM via mma.sync tf32 (3xTF32):
// C[M,N] = A[M,1024] @ W[N,1024]^T (+Res), operands pre-split hi/lo
// 128x128 CTA tile, K-chunk 32, double-buffered cp.async
// ============================================================
#define TSTRIDE 36
#define TS   (128*TSTRIDE)      // floats per tile (4608)
#define BUFF (4*TS)             // floats per buffer (A_h, A_l, B_h, B_l)
#define GEMM_SMEM (2*BUFF*4)    // bytes = 147456

__global__ __launch_bounds__(256, 1) void gemm_mma_kernel(
    const float* __restrict__ Ah, const float* __restrict__ Al,
    const float* __restrict__ Bh, const float* __restrict__ Bl,
    const float* __restrict__ Res, float* __restrict__ C, int N)
{
    extern __shared__ __align__(16) float sm[];
    int tid = threadIdx.x;
    int m0 = blockIdx.y * 128, n0 = blockIdx.x * 128;
    int lane = tid & 31, wid = tid >> 5;
    int g = lane >> 2, t4 = lane & 3;
    int wm = wid & 3, wn = wid >> 2;

    float acc[2][8][4];
    #pragma unroll
    for (int mt = 0; mt < 2; mt++)
        #pragma unroll
        for (int nt = 0; nt < 8; nt++)
            #pragma unroll
            for (int r = 0; r < 4; r++) acc[mt][nt][r] = 0.0f;

    // ---- cp.async issue of one K-chunk into buffer ch&1 ----
    auto issue = [&](int ch) {
        int k0 = ch * 32;
        float* dst = sm + (ch & 1) * BUFF;
        #pragma unroll
        for (int i = 0; i < 16; i++) {
            int task = tid + i * 256;             // 4096 16B tasks
            int tile = task >> 10;
            int rem  = task & 1023;
            int row  = rem >> 3, seg = rem & 7;
            const float* src = (tile & 2) ? ((tile & 1) ? Bl : Bh)
                                          : ((tile & 1) ? Al : Ah);
            int grow = ((tile & 2) ? n0 : m0) + row;
            uint32_t sa = smem_u32(dst + tile * TS + row * TSTRIDE + seg * 4);
            cp16(sa, src + (size_t)grow * 1024 + k0 + seg * 4);
        }
        CP_COMMIT();
    };

    issue(0);
    for (int ch = 0; ch < 32; ch++) {
        if (ch + 1 < 32) { issue(ch + 1); CP_WAIT1(); }
        else             { CP_WAIT0(); }
        __syncthreads();

        const float* As_h = sm + (ch & 1) * BUFF;
        const float* As_l = As_h + TS;
        const float* Bs_h = As_l + TS;
        const float* Bs_l = Bs_h + TS;

        #pragma unroll
        for (int s = 0; s < 4; s++) {
            uint32_t a[2][2][4];
            #pragma unroll
            for (int mt = 0; mt < 2; mt++) {
                int o = (wm*32 + mt*16 + g) * TSTRIDE + s*8 + t4;
                a[mt][0][0] = __float_as_uint(As_h[o]);
                a[mt][0][1] = __float_as_uint(As_h[o + 8*TSTRIDE]);
                a[mt][0][2] = __float_as_uint(As_h[o + 4]);
                a[mt][0][3] = __float_as_uint(As_h[o + 8*TSTRIDE + 4]);
                a[mt][1][0] = __float_as_uint(As_l[o]);
                a[mt][1][1] = __float_as_uint(As_l[o + 8*TSTRIDE]);
                a[mt][1][2] = __float_as_uint(As_l[o + 4]);
                a[mt][1][3] = __float_as_uint(As_l[o + 8*TSTRIDE + 4]);
            }
            #pragma unroll
            for (int nt = 0; nt < 8; nt++) {
                int o = (wn*64 + nt*8 + g) * TSTRIDE + s*8 + t4;
                uint32_t bh0 = __float_as_uint(Bs_h[o]);
                uint32_t bh1 = __float_as_uint(Bs_h[o + 4]);
                uint32_t bl0 = __float_as_uint(Bs_l[o]);
                uint32_t bl1 = __float_as_uint(Bs_l[o + 4]);
                #pragma unroll
                for (int mt = 0; mt < 2; mt++) {
                    mma_tf32(acc[mt][nt], a[mt][0], bh0, bh1);  // hi*hi
                    mma_tf32(acc[mt][nt], a[mt][0], bl0, bl1);  // hi*lo
                    mma_tf32(acc[mt][nt], a[mt][1], bh0, bh1);  // lo*hi
                }
            }
        }
        __syncthreads();
    }

    // ---- epilogue ----
    #pragma unroll
    for (int mt = 0; mt < 2; mt++) {
        int r0 = m0 + wm*32 + mt*16 + g;
        int r1 = r0 + 8;
        #pragma unroll
        for (int nt = 0; nt < 8; nt++) {
            int col = n0 + wn*64 + nt*8 + t4*2;
            float2 v0 = make_float2(acc[mt][nt][0], acc[mt][nt][1]);
            float2 v1 = make_float2(acc[mt][nt][2], acc[mt][nt][3]);
            if (Res) {
                float2 q0 = *(const float2*)(Res + (size_t)r0*N + col);
                float2 q1 = *(const float2*)(Res + (size_t)r1*N + col);
                v0.x += q0.x; v0.y += q0.y;
                v1.x += q1.x; v1.y += q1.y;
            }
            *(float2*)(C + (size_t)r0*N + col) = v0;
            *(float2*)(C + (size_t)r1*N + col) = v1;
        }
    }
}

// ============================================================
// RMSNorm -> tf32 hi/lo outputs
// ============================================================
__global__ __launch_bounds__(256) void rmsnorm_kernel(
    const float* __restrict__ x, const float* __restrict__ w,
    float* __restrict__ out_h, float* __restrict__ out_l)
{
    int row = blockIdx.x;
    int tid = threadIdx.x;
    const float4* xr = (const float4*)(x + (size_t)row*EMB);
    float4 v = xr[tid];
    float ss = v.x*v.x + v.y*v.y + v.z*v.z + v.w*v.w;
    #pragma unroll
    for (int o = 16; o > 0; o >>= 1) ss += __shfl_xor_sync(0xffffffffu, ss, o);
    __shared__ float wsum[8];
    if ((tid & 31) == 0) wsum[tid >> 5] = ss;
    __syncthreads();
    if (tid < 8) {
        float t = wsum[tid];
        #pragma unroll
        for (int o = 4; o > 0; o >>= 1) t += __shfl_xor_sync(0xffu, t, o);
        if (tid == 0) wsum[0] = t;
    }
    __syncthreads();
    float inv = rsqrtf(wsum[0] * (1.0f/EMB) + EPS);
    float4 wv = ((const float4*)w)[tid];
    float4 o4, h4, l4;
    o4.x = v.x*inv*wv.x; o4.y = v.y*inv*wv.y;
    o4.z = v.z*inv*wv.z; o4.w = v.w*inv*wv.w;
    split_tf32(o4.x, h4.x, l4.x);
    split_tf32(o4.y, h4.y, l4.y);
    split_tf32(o4.z, h4.z, l4.z);
    split_tf32(o4.w, h4.w, l4.w);
    ((float4*)(out_h + (size_t)row*EMB))[tid] = h4;
    ((float4*)(out_l + (size_t)row*EMB))[tid] = l4;
}

// ============================================================
// RoPE in-place on q,k parts of qkv
// ============================================================
__global__ __launch_bounds__(256) void rope_kernel(
    float* __restrict__ qkv, const float* __restrict__ cosb,
    const float* __restrict__ sinb)
{
    int idx = blockIdx.x * blockDim.x + threadIdx.x;
    int d  = idx & 31;
    int h  = (idx >> 5) & 15;
    int m  = (idx >> 9) & 4095;
    int t  = idx >> 21;
    int s  = m & (SEQ - 1);
    float* p = qkv + (size_t)m*QKVN + t*EMB + h*HD;
    float x0 = p[d], x1 = p[d + 32];
    float c0 = cosb[s*HD + d],      c1 = cosb[s*HD + d + 32];
    float s0 = sinb[s*HD + d],      s1 = sinb[s*HD + d + 32];
    p[d]      = c0*x0 + s0*x1;
    p[d + 32] = c1*x1 + s1*x0;
}

// ============================================================
// Causal flash attention, fp32; epilogue writes tf32 hi/lo
// ============================================================
__global__ __launch_bounds__(256, 2) void flash_kernel(
    const float* __restrict__ qkv,
    float* __restrict__ attn_h, float* __restrict__ attn_l)
{
    __shared__ float k_s[64*KPAD];
    __shared__ float v_s[64*KPAD];

    int qt = blockIdx.x, h = blockIdx.y, b = blockIdx.z;
    int tid = threadIdx.x;
    int qr = tid >> 2, c4 = tid & 3;
    int qm0 = b*SEQ + qt*64;

    const float* qbase = qkv + (size_t)qm0*QKVN + h*HD;
    for (int i = tid; i < 64*16; i += 256) {
        int row = i >> 4, d4 = i & 15;
        float4 v = *(const float4*)(qbase + (size_t)row*QKVN + d4*4);
        *(float4*)&k_s[row*KPAD + d4*4] = v;
    }
    __syncthreads();
    float4 q4[16];
    #pragma unroll
    for (int d4 = 0; d4 < 16; d4++) {
        float4 t = *(float4*)&k_s[qr*KPAD + d4*4];
        q4[d4].x = t.x*0.125f; q4[d4].y = t.y*0.125f;
        q4[d4].z = t.z*0.125f; q4[d4].w = t.w*0.125f;
    }

    float m_i = -INFINITY, l_i = 0.0f;
    float4 o4[4];
    #pragma unroll
    for (int jj = 0; jj < 4; jj++) o4[jj] = make_float4(0.f,0.f,0.f,0.f);

    const float* kbase = qkv + (size_t)b*SEQ*QKVN + EMB   + h*HD;
    const float* vbase = qkv + (size_t)b*SEQ*QKVN + 2*EMB + h*HD;

    for (int kt = 0; kt <= qt; kt++) {
        __syncthreads();
        int km0 = kt*64;
        for (int i = tid; i < 64*16; i += 256) {
            int row = i >> 4, d4 = i & 15;
            float4 kv = *(const float4*)(kbase + (size_t)(km0+row)*QKVN + d4*4);
            float4 vv = *(const float4*)(vbase + (size_t)(km0+row)*QKVN + d4*4);
            *(float4*)&k_s[row*KPAD + d4*4] = kv;
            *(float4*)&v_s[row*KPAD + d4*4] = vv;
        }
        __syncthreads();

        float sj[16];
        bool diag = (kt == qt);
        #pragma unroll
        for (int j = 0; j < 16; j++) {
            int col = c4 + 4*j;
            float4 a4 = make_float4(0.f,0.f,0.f,0.f);
            #pragma unroll
            for (int d4 = 0; d4 < 16; d4++) {
                float4 k4 = *(float4*)&k_s[col*KPAD + d4*4];
                a4.x = fmaf(q4[d4].x, k4.x, a4.x);
                a4.y = fmaf(q4[d4].y, k4.y, a4.y);
                a4.z = fmaf(q4[d4].z, k4.z, a4.z);
                a4.w = fmaf(q4[d4].w, k4.w, a4.w);
            }
            float a = (a4.x + a4.y) + (a4.z + a4.w);
            if (diag && col > qr) a = -INFINITY;
            sj[j] = a;
        }

        float mt = sj[0];
        #pragma unroll
        for (int j = 1; j < 16; j++) mt = fmaxf(mt, sj[j]);
        mt = fmaxf(mt, __shfl_xor_sync(0xffffffffu, mt, 1));
        mt = fmaxf(mt, __shfl_xor_sync(0xffffffffu, mt, 2));
        float m_new = fmaxf(m_i, mt);
        float lsum = 0.0f;
        #pragma unroll
        for (int j = 0; j < 16; j++) {
            sj[j] = __expf(sj[j] - m_new);
            lsum += sj[j];
        }
        lsum += __shfl_xor_sync(0xffffffffu, lsum, 1);
        lsum += __shfl_xor_sync(0xffffffffu, lsum, 2);
        float corr = __expf(m_i - m_new);
        l_i = l_i * corr + lsum;
        m_i = m_new;
        #pragma unroll
        for (int jj = 0; jj < 4; jj++) {
            o4[jj].x *= corr; o4[jj].y *= corr;
            o4[jj].z *= corr; o4[jj].w *= corr;
        }

        __syncthreads();
        #pragma unroll
        for (int j = 0; j < 16; j++)
            k_s[qr*KPAD + (c4 + 4*j)] = sj[j];
        __syncthreads();

        #pragma unroll 4
        for (int col = 0; col < 64; col++) {
            float p = k_s[qr*KPAD + col];
            #pragma unroll
            for (int jj = 0; jj < 4; jj++) {
                float4 v4 = *(float4*)&v_s[col*KPAD + jj*16 + c4*4];
                o4[jj].x = fmaf(p, v4.x, o4[jj].x);
                o4[jj].y = fmaf(p, v4.y, o4[jj].y);
                o4[jj].z = fmaf(p, v4.z, o4[jj].z);
                o4[jj].w = fmaf(p, v4.w, o4[jj].w);
            }
        }
    }

    float inv_l = 1.0f / l_i;
    size_t ob = (size_t)(qm0 + qr)*EMB + h*HD;
    #pragma unroll
    for (int jj = 0; jj < 4; jj++) {
        float4 h4, l4;
        split_tf32(o4[jj].x*inv_l, h4.x, l4.x);
        split_tf32(o4[jj].y*inv_l, h4.y, l4.y);
        split_tf32(o4[jj].z*inv_l, h4.z, l4.z);
        split_tf32(o4[jj].w*inv_l, h4.w, l4.w);
        *(float4*)(attn_h + ob + jj*16 + c4*4) = h4;
        *(float4*)(attn_l + ob + jj*16 + c4*4) = l4;
    }
}

// ============================================================
// launch
// ============================================================
extern "C" void kernel_launch(void* const* d_in, const int* in_sizes, int n_in,
                              void* d_out, int out_size)
{
    const float* emb  = (const float*)d_in[0];
    const float* cosb = (const float*)d_in[1];
    const float* sinb = (const float*)d_in[2];
    const float* nw   = (const float*)d_in[3];
    const float* qkvw = (const float*)d_in[4];
    const float* ow   = (const float*)d_in[5];
    float* out = (float*)d_out;

    float *qkv, *nh, *nl, *ah, *al, *wqh, *wql, *woh, *wol;
    cudaGetSymbolAddress((void**)&qkv, g_qkv);
    cudaGetSymbolAddress((void**)&nh,  g_nrm_h);
    cudaGetSymbolAddress((void**)&nl,  g_nrm_l);
    cudaGetSymbolAddress((void**)&ah,  g_att_h);
    cudaGetSymbolAddress((void**)&al,  g_att_l);
    cudaGetSymbolAddress((void**)&wqh, g_wqkv_h);
    cudaGetSymbolAddress((void**)&wql, g_wqkv_l);
    cudaGetSymbolAddress((void**)&woh, g_wo_h);
    cudaGetSymbolAddress((void**)&wol, g_wo_l);

    cudaFuncSetAttribute(gemm_mma_kernel,
        cudaFuncAttributeMaxDynamicSharedMemorySize, GEMM_SMEM);

    // weight splits (every launch; weights are inputs)
    conv_tf32_kernel<<<(QKVN*EMB/4)/256, 256>>>(qkvw, wqh, wql);
    conv_tf32_kernel<<<(EMB*EMB/4)/256, 256>>>(ow, woh, wol);
    // 1) RMSNorm -> hi/lo
    rmsnorm_kernel<<<MROWS, 256>>>(emb, nw, nh, nl);
    // 2) QKV projection (mma.sync tf32 3x)
    gemm_mma_kernel<<<dim3(QKVN/128, MROWS/128), 256, GEMM_SMEM>>>(
        nh, nl, wqh, wql, nullptr, qkv, QKVN);
    // 3) RoPE
    rope_kernel<<<(2*MROWS*NH*32)/256, 256>>>(qkv, cosb, sinb);
    // 4) causal attention -> hi/lo
    flash_kernel<<<dim3(SEQ/64, NH, BATCH), 256>>>(qkv, ah, al);
    // 5) out projection + residual
    gemm_mma_kernel<<<dim3(EMB/128, MROWS/128), 256, GEMM_SMEM>>>(
        ah, al, woh, wol, emb, out, EMB);
}

// round 5
// speedup vs baseline: 2.1079x; 1.9305x over previous
#include <cuda_runtime.h>
#include <cuda_fp16.h>
#include <math.h>
#include <stdint.h>

#define EMB   1024
#define NH    16
#define HD    64
#define SEQ   2048
#define BATCH 2
#define MROWS (BATCH*SEQ)     // 4096
#define QKVN  (3*EMB)         // 3072
#define EPS   1.1920929e-07f

// ---- scratch (no allocations allowed) ----
__device__ float  g_qkv[(size_t)MROWS*QKVN];
__device__ float  g_nrm_h[(size_t)MROWS*EMB];
__device__ float  g_nrm_l[(size_t)MROWS*EMB];
__device__ float  g_att_h[(size_t)MROWS*EMB];
__device__ float  g_att_l[(size_t)MROWS*EMB];
__device__ float  g_wqkv_h[(size_t)QKVN*EMB];
__device__ float  g_wqkv_l[(size_t)QKVN*EMB];
__device__ float  g_wo_h[(size_t)EMB*EMB];
__device__ float  g_wo_l[(size_t)EMB*EMB];
__device__ float  g_qh[(size_t)BATCH*NH*SEQ*HD];
__device__ float  g_ql[(size_t)BATCH*NH*SEQ*HD];
__device__ float  g_kh[(size_t)BATCH*NH*SEQ*HD];
__device__ float  g_kl[(size_t)BATCH*NH*SEQ*HD];
__device__ __half g_vth[(size_t)BATCH*NH*HD*SEQ];
__device__ __half g_vtl[(size_t)BATCH*NH*HD*SEQ];

// ============================================================
// helpers
// ============================================================
__device__ __forceinline__ uint32_t smem_u32(const void* p) {
    uint32_t a;
    asm("{ .reg .u64 t; cvta.to.shared.u64 t, %1; cvt.u32.u64 %0, t; }" : "=r"(a) : "l"(p));
    return a;
}
__device__ __forceinline__ uint32_t f2tf32(float x) {
    uint32_t r; asm("cvt.rna.tf32.f32 %0, %1;" : "=r"(r) : "f"(x)); return r;
}
__device__ __forceinline__ void split_tf32(float x, float& hi, float& lo) {
    uint32_t h = f2tf32(x);
    hi = __uint_as_float(h);
    lo = __uint_as_float(f2tf32(x - hi));
}
__device__ __forceinline__ void mma_tf32(float* c, const uint32_t* a,
                                         uint32_t b0, uint32_t b1) {
    asm volatile(
        "mma.sync.aligned.m16n8k8.row.col.f32.tf32.tf32.f32 "
        "{%0,%1,%2,%3}, {%4,%5,%6,%7}, {%8,%9}, {%0,%1,%2,%3};"
        : "+f"(c[0]), "+f"(c[1]), "+f"(c[2]), "+f"(c[3])
        : "r"(a[0]), "r"(a[1]), "r"(a[2]), "r"(a[3]), "r"(b0), "r"(b1));
}
__device__ __forceinline__ void mma_f16(float* c, const uint32_t* a,
                                        uint32_t b0, uint32_t b1) {
    asm volatile(
        "mma.sync.aligned.m16n8k16.row.col.f32.f16.f16.f32 "
        "{%0,%1,%2,%3}, {%4,%5,%6,%7}, {%8,%9}, {%0,%1,%2,%3};"
        : "+f"(c[0]), "+f"(c[1]), "+f"(c[2]), "+f"(c[3])
        : "r"(a[0]), "r"(a[1]), "r"(a[2]), "r"(a[3]), "r"(b0), "r"(b1));
}
__device__ __forceinline__ void cp16(uint32_t sdst, const void* gsrc) {
    asm volatile("cp.async.cg.shared.global [%0], [%1], 16;" :: "r"(sdst), "l"(gsrc));
}
#define CP_COMMIT() asm volatile("cp.async.commit_group;")
#define CP_WAIT1()  asm volatile("cp.async.wait_group 1;")
#define CP_WAIT0()  asm volatile("cp.async.wait_group 0;")

// ============================================================
// weight tf32 hi/lo split
// ============================================================
__global__ __launch_bounds__(256) void conv_tf32_kernel(
    const float* __restrict__ x, float* __restrict__ hi, float* __restrict__ lo)
{
    int i = blockIdx.x * 256 + threadIdx.x;
    float4 v = ((const float4*)x)[i];
    float4 h4, l4;
    split_tf32(v.x, h4.x, l4.x);
    split_tf32(v.y, h4.y, l4.y);
    split_tf32(v.z, h4.z, l4.z);
    split_tf32(v.w, h4.w, l4.w);
    ((float4*)hi)[i] = h4;
    ((float4*)lo)[i] = l4;
}

// ============================================================
// GEMM via mma.sync tf32 (3xTF32): C = A @ W^T (+Res)
// ============================================================
#define TSTRIDE 36
#define TS   (128*TSTRIDE)
#define BUFF (4*TS)
#define GEMM_SMEM (2*BUFF*4)

__global__ __launch_bounds__(256, 1) void gemm_mma_kernel(
    const float* __restrict__ Ah, const float* __restrict__ Al,
    const float* __restrict__ Bh, const float* __restrict__ Bl,
    const float* __restrict__ Res, float* __restrict__ C, int N)
{
    extern __shared__ __align__(16) float sm[];
    int tid = threadIdx.x;
    int m0 = blockIdx.y * 128, n0 = blockIdx.x * 128;
    int lane = tid & 31, wid = tid >> 5;
    int g = lane >> 2, t4 = lane & 3;
    int wm = wid & 3, wn = wid >> 2;

    float acc[2][8][4];
    #pragma unroll
    for (int mt = 0; mt < 2; mt++)
        #pragma unroll
        for (int nt = 0; nt < 8; nt++)
            #pragma unroll
            for (int r = 0; r < 4; r++) acc[mt][nt][r] = 0.0f;

    auto issue = [&](int ch) {
        int k0 = ch * 32;
        float* dst = sm + (ch & 1) * BUFF;
        #pragma unroll
        for (int i = 0; i < 16; i++) {
            int task = tid + i * 256;
            int tile = task >> 10;
            int rem  = task & 1023;
            int row  = rem >> 3, seg = rem & 7;
            const float* src = (tile & 2) ? ((tile & 1) ? Bl : Bh)
                                          : ((tile & 1) ? Al : Ah);
            int grow = ((tile & 2) ? n0 : m0) + row;
            uint32_t sa = smem_u32(dst + tile * TS + row * TSTRIDE + seg * 4);
            cp16(sa, src + (size_t)grow * 1024 + k0 + seg * 4);
        }
        CP_COMMIT();
    };

    issue(0);
    for (int ch = 0; ch < 32; ch++) {
        if (ch + 1 < 32) { issue(ch + 1); CP_WAIT1(); }
        else             { CP_WAIT0(); }
        __syncthreads();

        const float* As_h = sm + (ch & 1) * BUFF;
        const float* As_l = As_h + TS;
        const float* Bs_h = As_l + TS;
        const float* Bs_l = Bs_h + TS;

        #pragma unroll
        for (int s = 0; s < 4; s++) {
            uint32_t a[2][2][4];
            #pragma unroll
            for (int mt = 0; mt < 2; mt++) {
                int o = (wm*32 + mt*16 + g) * TSTRIDE + s*8 + t4;
                a[mt][0][0] = __float_as_uint(As_h[o]);
                a[mt][0][1] = __float_as_uint(As_h[o + 8*TSTRIDE]);
                a[mt][0][2] = __float_as_uint(As_h[o + 4]);
                a[mt][0][3] = __float_as_uint(As_h[o + 8*TSTRIDE + 4]);
                a[mt][1][0] = __float_as_uint(As_l[o]);
                a[mt][1][1] = __float_as_uint(As_l[o + 8*TSTRIDE]);
                a[mt][1][2] = __float_as_uint(As_l[o + 4]);
                a[mt][1][3] = __float_as_uint(As_l[o + 8*TSTRIDE + 4]);
            }
            #pragma unroll
            for (int nt = 0; nt < 8; nt++) {
                int o = (wn*64 + nt*8 + g) * TSTRIDE + s*8 + t4;
                uint32_t bh0 = __float_as_uint(Bs_h[o]);
                uint32_t bh1 = __float_as_uint(Bs_h[o + 4]);
                uint32_t bl0 = __float_as_uint(Bs_l[o]);
                uint32_t bl1 = __float_as_uint(Bs_l[o + 4]);
                #pragma unroll
                for (int mt = 0; mt < 2; mt++) {
                    mma_tf32(acc[mt][nt], a[mt][0], bh0, bh1);
                    mma_tf32(acc[mt][nt], a[mt][0], bl0, bl1);
                    mma_tf32(acc[mt][nt], a[mt][1], bh0, bh1);
                }
            }
        }
        __syncthreads();
    }

    #pragma unroll
    for (int mt = 0; mt < 2; mt++) {
        int r0 = m0 + wm*32 + mt*16 + g;
        int r1 = r0 + 8;
        #pragma unroll
        for (int nt = 0; nt < 8; nt++) {
            int col = n0 + wn*64 + nt*8 + t4*2;
            float2 v0 = make_float2(acc[mt][nt][0], acc[mt][nt][1]);
            float2 v1 = make_float2(acc[mt][nt][2], acc[mt][nt][3]);
            if (Res) {
                float2 q0 = *(const float2*)(Res + (size_t)r0*N + col);
                float2 q1 = *(const float2*)(Res + (size_t)r1*N + col);
                v0.x += q0.x; v0.y += q0.y;
                v1.x += q1.x; v1.y += q1.y;
            }
            *(float2*)(C + (size_t)r0*N + col) = v0;
            *(float2*)(C + (size_t)r1*N + col) = v1;
        }
    }
}

// ============================================================
// RMSNorm -> tf32 hi/lo
// ============================================================
__global__ __launch_bounds__(256) void rmsnorm_kernel(
    const float* __restrict__ x, const float* __restrict__ w,
    float* __restrict__ out_h, float* __restrict__ out_l)
{
    int row = blockIdx.x;
    int tid = threadIdx.x;
    const float4* xr = (const float4*)(x + (size_t)row*EMB);
    float4 v = xr[tid];
    float ss = v.x*v.x + v.y*v.y + v.z*v.z + v.w*v.w;
    #pragma unroll
    for (int o = 16; o > 0; o >>= 1) ss += __shfl_xor_sync(0xffffffffu, ss, o);
    __shared__ float wsum[8];
    if ((tid & 31) == 0) wsum[tid >> 5] = ss;
    __syncthreads();
    if (tid < 8) {
        float t = wsum[tid];
        #pragma unroll
        for (int o = 4; o > 0; o >>= 1) t += __shfl_xor_sync(0xffu, t, o);
        if (tid == 0) wsum[0] = t;
    }
    __syncthreads();
    float inv = rsqrtf(wsum[0] * (1.0f/EMB) + EPS);
    float4 wv = ((const float4*)w)[tid];
    float4 o4, h4, l4;
    o4.x = v.x*inv*wv.x; o4.y = v.y*inv*wv.y;
    o4.z = v.z*inv*wv.z; o4.w = v.w*inv*wv.w;
    split_tf32(o4.x, h4.x, l4.x);
    split_tf32(o4.y, h4.y, l4.y);
    split_tf32(o4.z, h4.z, l4.z);
    split_tf32(o4.w, h4.w, l4.w);
    ((float4*)(out_h + (size_t)row*EMB))[tid] = h4;
    ((float4*)(out_l + (size_t)row*EMB))[tid] = l4;
}

// ============================================================
// prep_qk: RoPE + (q: scale 1/8) + tf32 split -> [bh][s][64]
// ============================================================
__global__ __launch_bounds__(256) void prep_qk_kernel(
    const float* __restrict__ qkv, const float* __restrict__ cosb,
    const float* __restrict__ sinb,
    float* __restrict__ qh, float* __restrict__ ql,
    float* __restrict__ kh, float* __restrict__ kl)
{
    int idx = blockIdx.x * blockDim.x + threadIdx.x;   // 2^22
    int d  = idx & 31;
    int h  = (idx >> 5) & 15;
    int m  = (idx >> 9) & 4095;
    int t  = idx >> 21;                 // 0=q, 1=k
    int s  = m & (SEQ - 1);
    int b  = m >> 11;
    const float* p = qkv + (size_t)m*QKVN + t*EMB + h*HD;
    float x0 = p[d], x1 = p[d + 32];
    float c0 = cosb[s*HD + d],      c1 = cosb[s*HD + d + 32];
    float s0 = sinb[s*HD + d],      s1 = sinb[s*HD + d + 32];
    float r0 = c0*x0 + s0*x1;
    float r1 = c1*x1 + s1*x0;
    float* oh = (t ? kh : qh);
    float* ol = (t ? kl : ql);
    if (t == 0) { r0 *= 0.125f; r1 *= 0.125f; }
    size_t base = ((size_t)(b*NH + h)*SEQ + s)*HD;
    float h0, l0, h1, l1;
    split_tf32(r0, h0, l0);
    split_tf32(r1, h1, l1);
    oh[base + d]      = h0;  ol[base + d]      = l0;
    oh[base + d + 32] = h1;  ol[base + d + 32] = l1;
}

// ============================================================
// prep_v: transpose V to [bh][d][s], fp16 hi/lo
// ============================================================
__global__ __launch_bounds__(256) void prep_v_kernel(
    const float* __restrict__ qkv, __half* __restrict__ vth, __half* __restrict__ vtl)
{
    int idx = blockIdx.x * blockDim.x + threadIdx.x;   // 2^22
    int s  = idx & 2047;
    int d  = (idx >> 11) & 63;
    int bh = idx >> 17;
    int b = bh >> 4, h = bh & 15;
    float v = qkv[(size_t)(b*SEQ + s)*QKVN + 2*EMB + h*HD + d];
    __half vh = __float2half_rn(v);
    __half vl = __float2half_rn(v - __half2float(vh));
    size_t o = ((size_t)bh*HD + d)*SEQ + s;
    vth[o] = vh;
    vtl[o] = vl;
}

// ============================================================
// Tensor-core causal flash attention
//  block: 128 q rows (8 warps x 16), k-tiles of 64
//  QK^T: 3xTF32 m16n8k8; PV: 3x fp16 m16n8k16 (P,V hi/lo)
// ============================================================
#define QROWS 128
#define KTILE 64
#define QSTR  68                    // q/k smem row stride (floats)
#define QSZ   (QROWS*QSTR)          // 8704
#define KSZ   (KTILE*QSTR)          // 4352
#define VSTR32 36                   // v smem row stride in u32 (72 halfs)
#define VSZ32 (KTILE*VSTR32)        // 2304
#define OFF_QH 0
#define OFF_QL QSZ
#define OFF_KH (2*QSZ)              // + buf*KSZ
#define OFF_KL (2*QSZ + 2*KSZ)      // + buf*KSZ
#define OFF_VH (2*QSZ + 4*KSZ)      // + buf*VSZ32 (u32 units)
#define OFF_VL (2*QSZ + 4*KSZ + 2*VSZ32)
#define FLASH_SMEM ((2*QSZ + 4*KSZ + 4*VSZ32)*4)   // 176128 bytes

__global__ __launch_bounds__(256, 1) void flash_mma_kernel(
    const float* __restrict__ Qh, const float* __restrict__ Ql,
    const float* __restrict__ Kh, const float* __restrict__ Kl,
    const __half* __restrict__ Vth, const __half* __restrict__ Vtl,
    float* __restrict__ attn_h, float* __restrict__ attn_l)
{
    extern __shared__ __align__(16) float sm[];
    uint32_t sbase = smem_u32(sm);
    int tid = threadIdx.x, lane = tid & 31, wid = tid >> 5;
    int g = lane >> 2, t4 = lane & 3;
    int qt = (gridDim.x - 1) - blockIdx.x;       // heavy tiles first
    int h = blockIdx.y, b = blockIdx.z;
    int bh = b*NH + h;
    int q0 = qt * QROWS;
    int nkt = 2*(qt + 1);

    const float*  gQh = Qh  + (size_t)bh*SEQ*HD;
    const float*  gQl = Ql  + (size_t)bh*SEQ*HD;
    const float*  gKh = Kh  + (size_t)bh*SEQ*HD;
    const float*  gKl = Kl  + (size_t)bh*SEQ*HD;
    const __half* gVh = Vth + (size_t)bh*HD*SEQ;
    const __half* gVl = Vtl + (size_t)bh*HD*SEQ;

    auto issueKV = [&](int kt) {
        int k0 = kt * KTILE;
        int buf = kt & 1;
        #pragma unroll
        for (int i = 0; i < 8; i++) {            // K hi/lo: 2048 chunks
            int task = tid + i*256;
            int piece = task >> 10, rem = task & 1023;
            int row = rem >> 4, seg = rem & 15;
            const float* src = (piece ? gKl : gKh) + (size_t)(k0 + row)*HD + seg*4;
            uint32_t dst = sbase + ((piece ? OFF_KL : OFF_KH) + buf*KSZ + row*QSTR + seg*4)*4;
            cp16(dst, src);
        }
        #pragma unroll
        for (int i = 0; i < 4; i++) {            // V hi/lo: 1024 chunks
            int task = tid + i*256;
            int piece = task >> 9, rem = task & 511;
            int row = rem >> 3, seg = rem & 7;   // row=d, seg: 8 halfs
            const __half* src = (piece ? gVl : gVh) + (size_t)row*SEQ + k0 + seg*8;
            uint32_t dst = sbase + ((piece ? OFF_VL : OFF_VH) + buf*VSZ32 + row*VSTR32 + seg*4)*4;
            cp16(dst, src);
        }
    };

    // stage Q + first KV tile (group 0)
    #pragma unroll
    for (int i = 0; i < 16; i++) {
        int task = tid + i*256;
        int piece = task >> 11, rem = task & 2047;
        int row = rem >> 4, seg = rem & 15;
        const float* src = (piece ? gQl : gQh) + (size_t)(q0 + row)*HD + seg*4;
        uint32_t dst = sbase + ((piece ? OFF_QL : OFF_QH) + row*QSTR + seg*4)*4;
        cp16(dst, src);
    }
    issueKV(0);
    CP_COMMIT();

    float m0 = -INFINITY, m1 = -INFINITY, l0 = 0.f, l1 = 0.f;
    float o[8][4];
    #pragma unroll
    for (int dt = 0; dt < 8; dt++)
        #pragma unroll
        for (int e = 0; e < 4; e++) o[dt][e] = 0.f;

    const float* QhS = sm + OFF_QH;
    const float* QlS = sm + OFF_QL;
    int qrow = (wid*16 + g) * QSTR;

    for (int kt = 0; kt < nkt; kt++) {
        if (kt + 1 < nkt) { issueKV(kt + 1); CP_COMMIT(); CP_WAIT1(); }
        else              { CP_WAIT0(); }
        __syncthreads();

        int buf = kt & 1;
        const float* KhS = sm + OFF_KH + buf*KSZ;
        const float* KlS = sm + OFF_KL + buf*KSZ;
        const uint32_t* VhS = (const uint32_t*)sm + OFF_VH + buf*VSZ32;
        const uint32_t* VlS = (const uint32_t*)sm + OFF_VL + buf*VSZ32;

        // ---- scores: 3xTF32 ----
        float sc[8][4];
        #pragma unroll
        for (int nt = 0; nt < 8; nt++)
            #pragma unroll
            for (int e = 0; e < 4; e++) sc[nt][e] = 0.f;

        #pragma unroll
        for (int s = 0; s < 8; s++) {
            int qo = qrow + s*8 + t4;
            uint32_t aH[4] = {
                __float_as_uint(QhS[qo]),          __float_as_uint(QhS[qo + 8*QSTR]),
                __float_as_uint(QhS[qo + 4]),      __float_as_uint(QhS[qo + 8*QSTR + 4]) };
            uint32_t aL[4] = {
                __float_as_uint(QlS[qo]),          __float_as_uint(QlS[qo + 8*QSTR]),
                __float_as_uint(QlS[qo + 4]),      __float_as_uint(QlS[qo + 8*QSTR + 4]) };
            #pragma unroll
            for (int nt = 0; nt < 8; nt++) {
                int ko = (nt*8 + g)*QSTR + s*8 + t4;
                uint32_t bh0 = __float_as_uint(KhS[ko]);
                uint32_t bh1 = __float_as_uint(KhS[ko + 4]);
                uint32_t bl0 = __float_as_uint(KlS[ko]);
                uint32_t bl1 = __float_as_uint(KlS[ko + 4]);
                mma_tf32(sc[nt], aH, bh0, bh1);
                mma_tf32(sc[nt], aH, bl0, bl1);
                mma_tf32(sc[nt], aL, bh0, bh1);
            }
        }

        // ---- causal mask (diag region only) ----
        if (kt >= 2*qt) {
            int cb = kt*KTILE;
            int r0 = q0 + wid*16 + g, r1 = r0 + 8;
            #pragma unroll
            for (int nt = 0; nt < 8; nt++) {
                int c0 = cb + nt*8 + 2*t4;
                if (c0     > r0) sc[nt][0] = -INFINITY;
                if (c0 + 1 > r0) sc[nt][1] = -INFINITY;
                if (c0     > r1) sc[nt][2] = -INFINITY;
                if (c0 + 1 > r1) sc[nt][3] = -INFINITY;
            }
        }

        // ---- online softmax (2 rows per thread) ----
        float mt0 = -INFINITY, mt1 = -INFINITY;
        #pragma unroll
        for (int nt = 0; nt < 8; nt++) {
            mt0 = fmaxf(mt0, fmaxf(sc[nt][0], sc[nt][1]));
            mt1 = fmaxf(mt1, fmaxf(sc[nt][2], sc[nt][3]));
        }
        mt0 = fmaxf(mt0, __shfl_xor_sync(0xffffffffu, mt0, 1));
        mt0 = fmaxf(mt0, __shfl_xor_sync(0xffffffffu, mt0, 2));
        mt1 = fmaxf(mt1, __shfl_xor_sync(0xffffffffu, mt1, 1));
        mt1 = fmaxf(mt1, __shfl_xor_sync(0xffffffffu, mt1, 2));
        float mn0 = fmaxf(m0, mt0), mn1 = fmaxf(m1, mt1);
        float corr0 = __expf(m0 - mn0), corr1 = __expf(m1 - mn1);
        m0 = mn0; m1 = mn1;

        float ls0 = 0.f, ls1 = 0.f;
        uint32_t phA[8], phB[8], plA[8], plB[8];
        #pragma unroll
        for (int nt = 0; nt < 8; nt++) {
            float p0 = __expf(sc[nt][0] - mn0);
            float p1 = __expf(sc[nt][1] - mn0);
            float p2 = __expf(sc[nt][2] - mn1);
            float p3 = __expf(sc[nt][3] - mn1);
            ls0 += p0 + p1;  ls1 += p2 + p3;
            __half2 hA = __floats2half2_rn(p0, p1);
            float2 fA = __half22float2(hA);
            __half2 lA = __floats2half2_rn(p0 - fA.x, p1 - fA.y);
            __half2 hB = __floats2half2_rn(p2, p3);
            float2 fB = __half22float2(hB);
            __half2 lB = __floats2half2_rn(p2 - fB.x, p3 - fB.y);
            phA[nt] = *(uint32_t*)&hA;  plA[nt] = *(uint32_t*)&lA;
            phB[nt] = *(uint32_t*)&hB;  plB[nt] = *(uint32_t*)&lB;
        }
        ls0 += __shfl_xor_sync(0xffffffffu, ls0, 1);
        ls0 += __shfl_xor_sync(0xffffffffu, ls0, 2);
        ls1 += __shfl_xor_sync(0xffffffffu, ls1, 1);
        ls1 += __shfl_xor_sync(0xffffffffu, ls1, 2);
        l0 = l0*corr0 + ls0;
        l1 = l1*corr1 + ls1;
        #pragma unroll
        for (int dt = 0; dt < 8; dt++) {
            o[dt][0] *= corr0; o[dt][1] *= corr0;
            o[dt][2] *= corr1; o[dt][3] *= corr1;
        }

        // ---- PV: 3x fp16 ----
        #pragma unroll
        for (int kk = 0; kk < 4; kk++) {
            uint32_t aH[4] = { phA[2*kk], phB[2*kk], phA[2*kk+1], phB[2*kk+1] };
            uint32_t aL[4] = { plA[2*kk], plB[2*kk], plA[2*kk+1], plB[2*kk+1] };
            #pragma unroll
            for (int dt = 0; dt < 8; dt++) {
                int vo = (dt*8 + g)*VSTR32 + kk*8 + t4;
                uint32_t vh0 = VhS[vo], vh1 = VhS[vo + 4];
                uint32_t vl0 = VlS[vo], vl1 = VlS[vo + 4];
                mma_f16(o[dt], aH, vh0, vh1);
                mma_f16(o[dt], aH, vl0, vl1);
                mma_f16(o[dt], aL, vh0, vh1);
            }
        }
        __syncthreads();
    }

    // ---- epilogue: normalize, tf32-split, store ----
    float il0 = 1.0f / l0, il1 = 1.0f / l1;
    int r0g = b*SEQ + q0 + wid*16 + g;
    int r1g = r0g + 8;
    int cbase = h*HD;
    #pragma unroll
    for (int dt = 0; dt < 8; dt++) {
        int c = cbase + dt*8 + 2*t4;
        float v0 = o[dt][0]*il0, v1 = o[dt][1]*il0;
        float v2 = o[dt][2]*il1, v3 = o[dt][3]*il1;
        float h0,l0f,h1,l1f,h2,l2f,h3,l3f;
        split_tf32(v0, h0, l0f);  split_tf32(v1, h1, l1f);
        split_tf32(v2, h2, l2f);  split_tf32(v3, h3, l3f);
        *(float2*)(attn_h + (size_t)r0g*EMB + c) = make_float2(h0, h1);
        *(float2*)(attn_l + (size_t)r0g*EMB + c) = make_float2(l0f, l1f);
        *(float2*)(attn_h + (size_t)r1g*EMB + c) = make_float2(h2, h3);
        *(float2*)(attn_l + (size_t)r1g*EMB + c) = make_float2(l2f, l3f);
    }
}

// ============================================================
// launch
// ============================================================
extern "C" void kernel_launch(void* const* d_in, const int* in_sizes, int n_in,
                              void* d_out, int out_size)
{
    const float* emb  = (const float*)d_in[0];
    const float* cosb = (const float*)d_in[1];
    const float* sinb = (const float*)d_in[2];
    const float* nw   = (const float*)d_in[3];
    const float* qkvw = (const float*)d_in[4];
    const float* ow   = (const float*)d_in[5];
    float* out = (float*)d_out;

    float *qkv, *nh, *nl, *ah, *al, *wqh, *wql, *woh, *wol;
    float *qh, *ql, *kh, *kl;
    __half *vth, *vtl;
    cudaGetSymbolAddress((void**)&qkv, g_qkv);
    cudaGetSymbolAddress((void**)&nh,  g_nrm_h);
    cudaGetSymbolAddress((void**)&nl,  g_nrm_l);
    cudaGetSymbolAddress((void**)&ah,  g_att_h);
    cudaGetSymbolAddress((void**)&al,  g_att_l);
    cudaGetSymbolAddress((void**)&wqh, g_wqkv_h);
    cudaGetSymbolAddress((void**)&wql, g_wqkv_l);
    cudaGetSymbolAddress((void**)&woh, g_wo_h);
    cudaGetSymbolAddress((void**)&wol, g_wo_l);
    cudaGetSymbolAddress((void**)&qh,  g_qh);
    cudaGetSymbolAddress((void**)&ql,  g_ql);
    cudaGetSymbolAddress((void**)&kh,  g_kh);
    cudaGetSymbolAddress((void**)&kl,  g_kl);
    cudaGetSymbolAddress((void**)&vth, g_vth);
    cudaGetSymbolAddress((void**)&vtl, g_vtl);

    cudaFuncSetAttribute(gemm_mma_kernel,
        cudaFuncAttributeMaxDynamicSharedMemorySize, GEMM_SMEM);
    cudaFuncSetAttribute(flash_mma_kernel,
        cudaFuncAttributeMaxDynamicSharedMemorySize, FLASH_SMEM);

    // weight splits
    conv_tf32_kernel<<<(QKVN*EMB/4)/256, 256>>>(qkvw, wqh, wql);
    conv_tf32_kernel<<<(EMB*EMB/4)/256, 256>>>(ow, woh, wol);
    // 1) RMSNorm -> hi/lo
    rmsnorm_kernel<<<MROWS, 256>>>(emb, nw, nh, nl);
    // 2) QKV projection
    gemm_mma_kernel<<<dim3(QKVN/128, MROWS/128), 256, GEMM_SMEM>>>(
        nh, nl, wqh, wql, nullptr, qkv, QKVN);
    // 3) prep: RoPE + splits; V transpose
    prep_qk_kernel<<<(2*MROWS*NH*32)/256, 256>>>(qkv, cosb, sinb, qh, ql, kh, kl);
    prep_v_kernel<<<(BATCH*NH*HD*SEQ)/256, 256>>>(qkv, vth, vtl);
    // 4) tensor-core causal attention
    flash_mma_kernel<<<dim3(SEQ/QROWS, NH, BATCH), 256, FLASH_SMEM>>>(
        qh, ql, kh, kl, vth, vtl, ah, al);
    // 5) out projection + residual
    gemm_mma_kernel<<<dim3(EMB/128, MROWS/128), 256, GEMM_SMEM>>>(
        ah, al, woh, wol, emb, out, EMB);
}

// round 6
// speedup vs baseline: 3.6080x; 1.7116x over previous
#include <cuda_runtime.h>
#include <cuda_fp16.h>
#include <math.h>
#include <stdint.h>

#define EMB   1024
#define NH    16
#define HD    64
#define SEQ   2048
#define BATCH 2
#define MROWS (BATCH*SEQ)     // 4096
#define QKVN  (3*EMB)         // 3072
#define EPS   1.1920929e-07f

// ---- scratch (no allocations allowed) ----
__device__ float  g_qkv[(size_t)MROWS*QKVN];
__device__ __half g_nrm_h[(size_t)MROWS*EMB];
__device__ __half g_nrm_l[(size_t)MROWS*EMB];
__device__ __half g_att_h[(size_t)MROWS*EMB];
__device__ __half g_att_l[(size_t)MROWS*EMB];
__device__ __half g_wqkv_h[(size_t)QKVN*EMB];
__device__ __half g_wqkv_l[(size_t)QKVN*EMB];
__device__ __half g_wo_h[(size_t)EMB*EMB];
__device__ __half g_wo_l[(size_t)EMB*EMB];
__device__ __half g_qh[(size_t)BATCH*NH*SEQ*HD];
__device__ __half g_ql[(size_t)BATCH*NH*SEQ*HD];
__device__ __half g_kh[(size_t)BATCH*NH*SEQ*HD];
__device__ __half g_kl[(size_t)BATCH*NH*SEQ*HD];
__device__ __half g_vth[(size_t)BATCH*NH*HD*SEQ];
__device__ __half g_vtl[(size_t)BATCH*NH*HD*SEQ];

// ============================================================
// helpers
// ============================================================
__device__ __forceinline__ uint32_t smem_u32(const void* p) {
    uint32_t a;
    asm("{ .reg .u64 t; cvta.to.shared.u64 t, %1; cvt.u32.u64 %0, t; }" : "=r"(a) : "l"(p));
    return a;
}
__device__ __forceinline__ void split_f16(float x, __half& h, __half& l) {
    h = __float2half_rn(x);
    l = __float2half_rn(x - __half2float(h));
}
__device__ __forceinline__ void mma_f16(float* c, const uint32_t* a,
                                        uint32_t b0, uint32_t b1) {
    asm volatile(
        "mma.sync.aligned.m16n8k16.row.col.f32.f16.f16.f32 "
        "{%0,%1,%2,%3}, {%4,%5,%6,%7}, {%8,%9}, {%0,%1,%2,%3};"
        : "+f"(c[0]), "+f"(c[1]), "+f"(c[2]), "+f"(c[3])
        : "r"(a[0]), "r"(a[1]), "r"(a[2]), "r"(a[3]), "r"(b0), "r"(b1));
}
__device__ __forceinline__ void cp16(uint32_t sdst, const void* gsrc) {
    asm volatile("cp.async.cg.shared.global [%0], [%1], 16;" :: "r"(sdst), "l"(gsrc));
}
#define CP_COMMIT() asm volatile("cp.async.commit_group;")
#define CP_WAIT1()  asm volatile("cp.async.wait_group 1;")
#define CP_WAIT0()  asm volatile("cp.async.wait_group 0;")

// ============================================================
// weight fp16 hi/lo split
// ============================================================
__global__ __launch_bounds__(256) void conv_f16_kernel(
    const float* __restrict__ x, __half* __restrict__ hi, __half* __restrict__ lo)
{
    int i = blockIdx.x * 256 + threadIdx.x;
    float4 v = ((const float4*)x)[i];
    __half hx, lx, hy, ly, hz, lz, hw, lw;
    split_f16(v.x, hx, lx);  split_f16(v.y, hy, ly);
    split_f16(v.z, hz, lz);  split_f16(v.w, hw, lw);
    __half2 h01 = __halves2half2(hx, hy), h23 = __halves2half2(hz, hw);
    __half2 l01 = __halves2half2(lx, ly), l23 = __halves2half2(lz, lw);
    uint2 hp, lp;
    hp.x = *(uint32_t*)&h01; hp.y = *(uint32_t*)&h23;
    lp.x = *(uint32_t*)&l01; lp.y = *(uint32_t*)&l23;
    *(uint2*)(hi + (size_t)i*4) = hp;
    *(uint2*)(lo + (size_t)i*4) = lp;
}

// ============================================================
// GEMM via mma.sync fp16 (3x hi/lo): C[M,N] = A[M,1024] @ W[N,1024]^T (+Res)
// 128x128 CTA tile, K-chunk 64, double-buffered cp.async
// smem tiles: 128 rows x 72 halfs (36 words), conflict-free fragments
// ============================================================
#define HSTRW 36                      // words (u32) per smem row
#define TW    (128*HSTRW)             // words per tile = 4608
#define BUFW  (4*TW)                  // words per buffer = 18432
#define GEMM_SMEM (2*BUFW*4)          // 147456 bytes

__global__ __launch_bounds__(256, 1) void gemm_f16_kernel(
    const __half* __restrict__ Ah, const __half* __restrict__ Al,
    const __half* __restrict__ Bh, const __half* __restrict__ Bl,
    const float* __restrict__ Res, float* __restrict__ C, int N)
{
    extern __shared__ __align__(16) uint32_t sg[];
    uint32_t sbase = smem_u32(sg);
    int tid = threadIdx.x;
    int m0 = blockIdx.y * 128, n0 = blockIdx.x * 128;
    int lane = tid & 31, wid = tid >> 5;
    int g = lane >> 2, t4 = lane & 3;
    int wm = wid & 3, wn = wid >> 2;

    float acc[2][8][4];
    #pragma unroll
    for (int mt = 0; mt < 2; mt++)
        #pragma unroll
        for (int nt = 0; nt < 8; nt++)
            #pragma unroll
            for (int r = 0; r < 4; r++) acc[mt][nt][r] = 0.0f;

    auto issue = [&](int ch) {
        int k0 = ch * 64;
        uint32_t bufw = (uint32_t)(ch & 1) * BUFW;
        #pragma unroll
        for (int i = 0; i < 16; i++) {
            int task = tid + i * 256;          // 4096 tasks (8 halfs each)
            int tile = task >> 10;
            int rem  = task & 1023;
            int row  = rem >> 3, seg = rem & 7;
            const __half* src = (tile == 0) ? Ah : (tile == 1) ? Al
                              : (tile == 2) ? Bh : Bl;
            int grow = ((tile < 2) ? m0 : n0) + row;
            uint32_t sa = sbase + (bufw + tile*TW + row*HSTRW + seg*4)*4;
            cp16(sa, src + (size_t)grow*1024 + k0 + seg*8);
        }
        CP_COMMIT();
    };

    issue(0);
    for (int ch = 0; ch < 16; ch++) {
        if (ch + 1 < 16) { issue(ch + 1); CP_WAIT1(); }
        else             { CP_WAIT0(); }
        __syncthreads();

        const uint32_t* AsH = sg + (ch & 1)*BUFW;
        const uint32_t* AsL = AsH + TW;
        const uint32_t* BsH = AsL + TW;
        const uint32_t* BsL = BsH + TW;

        #pragma unroll
        for (int s = 0; s < 4; s++) {
            uint32_t aH[2][4], aL[2][4];
            #pragma unroll
            for (int mt = 0; mt < 2; mt++) {
                int o = (wm*32 + mt*16 + g)*HSTRW + s*8 + t4;
                aH[mt][0] = AsH[o];           aH[mt][1] = AsH[o + 8*HSTRW];
                aH[mt][2] = AsH[o + 4];       aH[mt][3] = AsH[o + 8*HSTRW + 4];
                aL[mt][0] = AsL[o];           aL[mt][1] = AsL[o + 8*HSTRW];
                aL[mt][2] = AsL[o + 4];       aL[mt][3] = AsL[o + 8*HSTRW + 4];
            }
            #pragma unroll
            for (int nt = 0; nt < 8; nt++) {
                int o = (wn*64 + nt*8 + g)*HSTRW + s*8 + t4;
                uint32_t bh0 = BsH[o], bh1 = BsH[o + 4];
                uint32_t bl0 = BsL[o], bl1 = BsL[o + 4];
                #pragma unroll
                for (int mt = 0; mt < 2; mt++) {
                    mma_f16(acc[mt][nt], aH[mt], bh0, bh1);
                    mma_f16(acc[mt][nt], aH[mt], bl0, bl1);
                    mma_f16(acc[mt][nt], aL[mt], bh0, bh1);
                }
            }
        }
        __syncthreads();
    }

    #pragma unroll
    for (int mt = 0; mt < 2; mt++) {
        int r0 = m0 + wm*32 + mt*16 + g;
        int r1 = r0 + 8;
        #pragma unroll
        for (int nt = 0; nt < 8; nt++) {
            int col = n0 + wn*64 + nt*8 + t4*2;
            float2 v0 = make_float2(acc[mt][nt][0], acc[mt][nt][1]);
            float2 v1 = make_float2(acc[mt][nt][2], acc[mt][nt][3]);
            if (Res) {
                float2 q0 = *(const float2*)(Res + (size_t)r0*N + col);
                float2 q1 = *(const float2*)(Res + (size_t)r1*N + col);
                v0.x += q0.x; v0.y += q0.y;
                v1.x += q1.x; v1.y += q1.y;
            }
            *(float2*)(C + (size_t)r0*N + col) = v0;
            *(float2*)(C + (size_t)r1*N + col) = v1;
        }
    }
}

// ============================================================
// RMSNorm -> fp16 hi/lo
// ============================================================
__global__ __launch_bounds__(256) void rmsnorm_kernel(
    const float* __restrict__ x, const float* __restrict__ w,
    __half* __restrict__ out_h, __half* __restrict__ out_l)
{
    int row = blockIdx.x;
    int tid = threadIdx.x;
    const float4* xr = (const float4*)(x + (size_t)row*EMB);
    float4 v = xr[tid];
    float ss = v.x*v.x + v.y*v.y + v.z*v.z + v.w*v.w;
    #pragma unroll
    for (int o = 16; o > 0; o >>= 1) ss += __shfl_xor_sync(0xffffffffu, ss, o);
    __shared__ float wsum[8];
    if ((tid & 31) == 0) wsum[tid >> 5] = ss;
    __syncthreads();
    if (tid < 8) {
        float t = wsum[tid];
        #pragma unroll
        for (int o = 4; o > 0; o >>= 1) t += __shfl_xor_sync(0xffu, t, o);
        if (tid == 0) wsum[0] = t;
    }
    __syncthreads();
    float inv = rsqrtf(wsum[0] * (1.0f/EMB) + EPS);
    float4 wv = ((const float4*)w)[tid];
    float4 o4;
    o4.x = v.x*inv*wv.x; o4.y = v.y*inv*wv.y;
    o4.z = v.z*inv*wv.z; o4.w = v.w*inv*wv.w;
    __half hx, lx, hy, ly, hz, lz, hw, lw;
    split_f16(o4.x, hx, lx);  split_f16(o4.y, hy, ly);
    split_f16(o4.z, hz, lz);  split_f16(o4.w, hw, lw);
    __half2 h01 = __halves2half2(hx, hy), h23 = __halves2half2(hz, hw);
    __half2 l01 = __halves2half2(lx, ly), l23 = __halves2half2(lz, lw);
    uint2 hp, lp;
    hp.x = *(uint32_t*)&h01; hp.y = *(uint32_t*)&h23;
    lp.x = *(uint32_t*)&l01; lp.y = *(uint32_t*)&l23;
    *(uint2*)(out_h + (size_t)row*EMB + tid*4) = hp;
    *(uint2*)(out_l + (size_t)row*EMB + tid*4) = lp;
}

// ============================================================
// prep_qk: RoPE + (q: scale 1/8) + fp16 split -> [bh][s][64]
// ============================================================
__global__ __launch_bounds__(256) void prep_qk_kernel(
    const float* __restrict__ qkv, const float* __restrict__ cosb,
    const float* __restrict__ sinb,
    __half* __restrict__ qh, __half* __restrict__ ql,
    __half* __restrict__ kh, __half* __restrict__ kl)
{
    int idx = blockIdx.x * blockDim.x + threadIdx.x;   // 2^22
    int d  = idx & 31;
    int h  = (idx >> 5) & 15;
    int m  = (idx >> 9) & 4095;
    int t  = idx >> 21;                 // 0=q, 1=k
    int s  = m & (SEQ - 1);
    int b  = m >> 11;
    const float* p = qkv + (size_t)m*QKVN + t*EMB + h*HD;
    float x0 = p[d], x1 = p[d + 32];
    float c0 = cosb[s*HD + d],      c1 = cosb[s*HD + d + 32];
    float s0 = sinb[s*HD + d],      s1 = sinb[s*HD + d + 32];
    float r0 = c0*x0 + s0*x1;
    float r1 = c1*x1 + s1*x0;
    if (t == 0) { r0 *= 0.125f; r1 *= 0.125f; }
    __half* oh = (t ? kh : qh);
    __half* ol = (t ? kl : ql);
    size_t base = ((size_t)(b*NH + h)*SEQ + s)*HD;
    __half h0, l0, h1, l1;
    split_f16(r0, h0, l0);
    split_f16(r1, h1, l1);
    oh[base + d]      = h0;  ol[base + d]      = l0;
    oh[base + d + 32] = h1;  ol[base + d + 32] = l1;
}

// ============================================================
// prep_v: tiled transpose V -> [bh][d][s], fp16 hi/lo
// block = (s-tile 64, h, b), 256 threads
// ============================================================
__global__ __launch_bounds__(256) void prep_v_kernel(
    const float* __restrict__ qkv, __half* __restrict__ vth, __half* __restrict__ vtl)
{
    __shared__ float ts[64*65];
    int st = blockIdx.x * 64, h = blockIdx.y, b = blockIdx.z;
    int tid = threadIdx.x;
    int row = tid >> 2, seg = tid & 3;
    const float* src = qkv + (size_t)(b*SEQ + st + row)*QKVN + 2*EMB + h*HD;
    #pragma unroll
    for (int j = 0; j < 4; j++) {
        int f4 = seg*4 + j;
        float4 v = *(const float4*)(src + f4*4);
        ts[row*65 + f4*4+0] = v.x; ts[row*65 + f4*4+1] = v.y;
        ts[row*65 + f4*4+2] = v.z; ts[row*65 + f4*4+3] = v.w;
    }
    __syncthreads();
    int d = tid >> 2, ss = tid & 3;     // thread writes 16 s values for dim d
    __half hv[16], lv[16];
    #pragma unroll
    for (int j = 0; j < 16; j++) {
        float v = ts[(ss*16 + j)*65 + d];
        split_f16(v, hv[j], lv[j]);
    }
    size_t ob = ((size_t)((b*NH + h)*HD) + d)*SEQ + st + ss*16;
    #pragma unroll
    for (int j = 0; j < 4; j++) {
        __half2 a = __halves2half2(hv[4*j], hv[4*j+1]);
        __half2 c = __halves2half2(hv[4*j+2], hv[4*j+3]);
        uint2 pk; pk.x = *(uint32_t*)&a; pk.y = *(uint32_t*)&c;
        *(uint2*)(vth + ob + 4*j) = pk;
        __half2 a2 = __halves2half2(lv[4*j], lv[4*j+1]);
        __half2 c2 = __halves2half2(lv[4*j+2], lv[4*j+3]);
        uint2 pl; pl.x = *(uint32_t*)&a2; pl.y = *(uint32_t*)&c2;
        *(uint2*)(vtl + ob + 4*j) = pl;
    }
}

// ============================================================
// Tensor-core causal flash attention (all fp16 hi/lo mma)
//  block: 128 q rows (8 warps x 16), k-tiles of 64
// ============================================================
#define QROWS 128
#define KSTRW 36                        // words per smem row (72 halfs)
#define QSZW  (QROWS*KSTRW)             // 4608 words
#define KSZW  (64*KSTRW)                // 2304 words
#define OFF_QH 0
#define OFF_QL QSZW
#define OFF_KH (2*QSZW)                 // + buf*KSZW  (2 bufs)
#define OFF_KL (2*QSZW + 2*KSZW)
#define OFF_VH (2*QSZW + 4*KSZW)
#define OFF_VL (2*QSZW + 6*KSZW)
#define FLASH_SMEM ((2*QSZW + 8*KSZW)*4)   // 110592 bytes

__global__ __launch_bounds__(256, 1) void flash_mma_kernel(
    const __half* __restrict__ Qh, const __half* __restrict__ Ql,
    const __half* __restrict__ Kh, const __half* __restrict__ Kl,
    const __half* __restrict__ Vth, const __half* __restrict__ Vtl,
    __half* __restrict__ attn_h, __half* __restrict__ attn_l)
{
    extern __shared__ __align__(16) uint32_t sf[];
    uint32_t sbase = smem_u32(sf);
    int tid = threadIdx.x, lane = tid & 31, wid = tid >> 5;
    int g = lane >> 2, t4 = lane & 3;
    int qt = (gridDim.x - 1) - blockIdx.x;       // heavy tiles first
    int h = blockIdx.y, b = blockIdx.z;
    int bh = b*NH + h;
    int q0 = qt * QROWS;
    int nkt = 2*(qt + 1);

    const __half* gQh = Qh  + (size_t)bh*SEQ*HD;
    const __half* gQl = Ql  + (size_t)bh*SEQ*HD;
    const __half* gKh = Kh  + (size_t)bh*SEQ*HD;
    const __half* gKl = Kl  + (size_t)bh*SEQ*HD;
    const __half* gVh = Vth + (size_t)bh*HD*SEQ;
    const __half* gVl = Vtl + (size_t)bh*HD*SEQ;

    auto issueKV = [&](int kt) {
        int k0 = kt * 64;
        uint32_t bufw = (uint32_t)(kt & 1) * KSZW;
        #pragma unroll
        for (int i = 0; i < 4; i++) {            // K hi/lo: 1024 tasks
            int task = tid + i*256;
            int piece = task >> 9, rem = task & 511;
            int row = rem >> 3, seg = rem & 7;
            const __half* src = (piece ? gKl : gKh) + (size_t)(k0 + row)*HD + seg*8;
            uint32_t dst = sbase + (((piece ? OFF_KL : OFF_KH) + bufw) + row*KSTRW + seg*4)*4;
            cp16(dst, src);
        }
        #pragma unroll
        for (int i = 0; i < 4; i++) {            // V hi/lo: 1024 tasks
            int task = tid + i*256;
            int piece = task >> 9, rem = task & 511;
            int row = rem >> 3, seg = rem & 7;   // row = d
            const __half* src = (piece ? gVl : gVh) + (size_t)row*SEQ + k0 + seg*8;
            uint32_t dst = sbase + (((piece ? OFF_VL : OFF_VH) + bufw) + row*KSTRW + seg*4)*4;
            cp16(dst, src);
        }
    };

    // stage Q (hi/lo) + first KV tile
    #pragma unroll
    for (int i = 0; i < 8; i++) {
        int task = tid + i*256;                  // 2048 tasks
        int piece = task >> 10, rem = task & 1023;
        int row = rem >> 3, seg = rem & 7;
        const __half* src = (piece ? gQl : gQh) + (size_t)(q0 + row)*HD + seg*8;
        uint32_t dst = sbase + ((piece ? OFF_QL : OFF_QH) + row*KSTRW + seg*4)*4;
        cp16(dst, src);
    }
    issueKV(0);
    CP_COMMIT();

    float m0 = -INFINITY, m1 = -INFINITY, l0 = 0.f, l1 = 0.f;
    float o[8][4];
    #pragma unroll
    for (int dt = 0; dt < 8; dt++)
        #pragma unroll
        for (int e = 0; e < 4; e++) o[dt][e] = 0.f;

    const uint32_t* QhS = sf + OFF_QH;
    const uint32_t* QlS = sf + OFF_QL;
    int qrow = (wid*16 + g) * KSTRW;

    for (int kt = 0; kt < nkt; kt++) {
        if (kt + 1 < nkt) { issueKV(kt + 1); CP_COMMIT(); CP_WAIT1(); }
        else              { CP_WAIT0(); }
        __syncthreads();

        uint32_t bufw = (uint32_t)(kt & 1) * KSZW;
        const uint32_t* KhS = sf + OFF_KH + bufw;
        const uint32_t* KlS = sf + OFF_KL + bufw;
        const uint32_t* VhS = sf + OFF_VH + bufw;
        const uint32_t* VlS = sf + OFF_VL + bufw;

        // ---- scores: 3x fp16 (4 k16-steps over d=64) ----
        float sc[8][4];
        #pragma unroll
        for (int nt = 0; nt < 8; nt++)
            #pragma unroll
            for (int e = 0; e < 4; e++) sc[nt][e] = 0.f;

        #pragma unroll
        for (int s = 0; s < 4; s++) {
            int qo = qrow + s*8 + t4;
            uint32_t aH[4] = { QhS[qo], QhS[qo + 8*KSTRW], QhS[qo + 4], QhS[qo + 8*KSTRW + 4] };
            uint32_t aL[4] = { QlS[qo], QlS[qo + 8*KSTRW], QlS[qo + 4], QlS[qo + 8*KSTRW + 4] };
            #pragma unroll
            for (int nt = 0; nt < 8; nt++) {
                int ko = (nt*8 + g)*KSTRW + s*8 + t4;
                uint32_t bh0 = KhS[ko], bh1 = KhS[ko + 4];
                uint32_t bl0 = KlS[ko], bl1 = KlS[ko + 4];
                mma_f16(sc[nt], aH, bh0, bh1);
                mma_f16(sc[nt], aH, bl0, bl1);
                mma_f16(sc[nt], aL, bh0, bh1);
            }
        }

        // ---- causal mask (diag region only) ----
        if (kt >= 2*qt) {
            int cb = kt*64;
            int r0 = q0 + wid*16 + g, r1 = r0 + 8;
            #pragma unroll
            for (int nt = 0; nt < 8; nt++) {
                int c0 = cb + nt*8 + 2*t4;
                if (c0     > r0) sc[nt][0] = -INFINITY;
                if (c0 + 1 > r0) sc[nt][1] = -INFINITY;
                if (c0     > r1) sc[nt][2] = -INFINITY;
                if (c0 + 1 > r1) sc[nt][3] = -INFINITY;
            }
        }

        // ---- online softmax ----
        float mt0 = -INFINITY, mt1 = -INFINITY;
        #pragma unroll
        for (int nt = 0; nt < 8; nt++) {
            mt0 = fmaxf(mt0, fmaxf(sc[nt][0], sc[nt][1]));
            mt1 = fmaxf(mt1, fmaxf(sc[nt][2], sc[nt][3]));
        }
        mt0 = fmaxf(mt0, __shfl_xor_sync(0xffffffffu, mt0, 1));
        mt0 = fmaxf(mt0, __shfl_xor_sync(0xffffffffu, mt0, 2));
        mt1 = fmaxf(mt1, __shfl_xor_sync(0xffffffffu, mt1, 1));
        mt1 = fmaxf(mt1, __shfl_xor_sync(0xffffffffu, mt1, 2));
        float mn0 = fmaxf(m0, mt0), mn1 = fmaxf(m1, mt1);
        float corr0 = __expf(m0 - mn0), corr1 = __expf(m1 - mn1);
        m0 = mn0; m1 = mn1;

        float ls0 = 0.f, ls1 = 0.f;
        uint32_t phA[8], phB[8], plA[8], plB[8];
        #pragma unroll
        for (int nt = 0; nt < 8; nt++) {
            float p0 = __expf(sc[nt][0] - mn0);
            float p1 = __expf(sc[nt][1] - mn0);
            float p2 = __expf(sc[nt][2] - mn1);
            float p3 = __expf(sc[nt][3] - mn1);
            ls0 += p0 + p1;  ls1 += p2 + p3;
            __half2 hA = __floats2half2_rn(p0, p1);
            float2 fA = __half22float2(hA);
            __half2 lA = __floats2half2_rn(p0 - fA.x, p1 - fA.y);
            __half2 hB = __floats2half2_rn(p2, p3);
            float2 fB = __half22float2(hB);
            __half2 lB = __floats2half2_rn(p2 - fB.x, p3 - fB.y);
            phA[nt] = *(uint32_t*)&hA;  plA[nt] = *(uint32_t*)&lA;
            phB[nt] = *(uint32_t*)&hB;  plB[nt] = *(uint32_t*)&lB;
        }
        ls0 += __shfl_xor_sync(0xffffffffu, ls0, 1);
        ls0 += __shfl_xor_sync(0xffffffffu, ls0, 2);
        ls1 += __shfl_xor_sync(0xffffffffu, ls1, 1);
        ls1 += __shfl_xor_sync(0xffffffffu, ls1, 2);
        l0 = l0*corr0 + ls0;
        l1 = l1*corr1 + ls1;
        #pragma unroll
        for (int dt = 0; dt < 8; dt++) {
            o[dt][0] *= corr0; o[dt][1] *= corr0;
            o[dt][2] *= corr1; o[dt][3] *= corr1;
        }

        // ---- PV: 3x fp16 ----
        #pragma unroll
        for (int kk = 0; kk < 4; kk++) {
            uint32_t aH[4] = { phA[2*kk], phB[2*kk], phA[2*kk+1], phB[2*kk+1] };
            uint32_t aL[4] = { plA[2*kk], plB[2*kk], plA[2*kk+1], plB[2*kk+1] };
            #pragma unroll
            for (int dt = 0; dt < 8; dt++) {
                int vo = (dt*8 + g)*KSTRW + kk*8 + t4;
                uint32_t vh0 = VhS[vo], vh1 = VhS[vo + 4];
                uint32_t vl0 = VlS[vo], vl1 = VlS[vo + 4];
                mma_f16(o[dt], aH, vh0, vh1);
                mma_f16(o[dt], aH, vl0, vl1);
                mma_f16(o[dt], aL, vh0, vh1);
            }
        }
        __syncthreads();
    }

    // ---- epilogue: normalize, fp16-split, store hi/lo ----
    float il0 = 1.0f / l0, il1 = 1.0f / l1;
    int r0g = b*SEQ + q0 + wid*16 + g;
    int r1g = r0g + 8;
    int cbase = h*HD;
    #pragma unroll
    for (int dt = 0; dt < 8; dt++) {
        int c = cbase + dt*8 + 2*t4;
        float v0 = o[dt][0]*il0, v1 = o[dt][1]*il0;
        float v2 = o[dt][2]*il1, v3 = o[dt][3]*il1;
        __half h0,l0h,h1,l1h,h2,l2h,h3,l3h;
        split_f16(v0, h0, l0h);  split_f16(v1, h1, l1h);
        split_f16(v2, h2, l2h);  split_f16(v3, h3, l3h);
        __half2 ha = __halves2half2(h0, h1), la = __halves2half2(l0h, l1h);
        __half2 hb = __halves2half2(h2, h3), lb = __halves2half2(l2h, l3h);
        *(uint32_t*)(attn_h + (size_t)r0g*EMB + c) = *(uint32_t*)&ha;
        *(uint32_t*)(attn_l + (size_t)r0g*EMB + c) = *(uint32_t*)&la;
        *(uint32_t*)(attn_h + (size_t)r1g*EMB + c) = *(uint32_t*)&hb;
        *(uint32_t*)(attn_l + (size_t)r1g*EMB + c) = *(uint32_t*)&lb;
    }
}

// ============================================================
// launch
// ============================================================
extern "C" void kernel_launch(void* const* d_in, const int* in_sizes, int n_in,
                              void* d_out, int out_size)
{
    const float* emb  = (const float*)d_in[0];
    const float* cosb = (const float*)d_in[1];
    const float* sinb = (const float*)d_in[2];
    const float* nw   = (const float*)d_in[3];
    const float* qkvw = (const float*)d_in[4];
    const float* ow   = (const float*)d_in[5];
    float* out = (float*)d_out;

    float* qkv;
    __half *nh, *nl, *ah, *al, *wqh, *wql, *woh, *wol;
    __half *qh, *ql, *kh, *kl, *vth, *vtl;
    cudaGetSymbolAddress((void**)&qkv, g_qkv);
    cudaGetSymbolAddress((void**)&nh,  g_nrm_h);
    cudaGetSymbolAddress((void**)&nl,  g_nrm_l);
    cudaGetSymbolAddress((void**)&ah,  g_att_h);
    cudaGetSymbolAddress((void**)&al,  g_att_l);
    cudaGetSymbolAddress((void**)&wqh, g_wqkv_h);
    cudaGetSymbolAddress((void**)&wql, g_wqkv_l);
    cudaGetSymbolAddress((void**)&woh, g_wo_h);
    cudaGetSymbolAddress((void**)&wol, g_wo_l);
    cudaGetSymbolAddress((void**)&qh,  g_qh);
    cudaGetSymbolAddress((void**)&ql,  g_ql);
    cudaGetSymbolAddress((void**)&kh,  g_kh);
    cudaGetSymbolAddress((void**)&kl,  g_kl);
    cudaGetSymbolAddress((void**)&vth, g_vth);
    cudaGetSymbolAddress((void**)&vtl, g_vtl);

    cudaFuncSetAttribute(gemm_f16_kernel,
        cudaFuncAttributeMaxDynamicSharedMemorySize, GEMM_SMEM);
    cudaFuncSetAttribute(flash_mma_kernel,
        cudaFuncAttributeMaxDynamicSharedMemorySize, FLASH_SMEM);

    // weight splits
    conv_f16_kernel<<<(QKVN*EMB/4)/256, 256>>>(qkvw, wqh, wql);
    conv_f16_kernel<<<(EMB*EMB/4)/256, 256>>>(ow, woh, wol);
    // 1) RMSNorm -> hi/lo
    rmsnorm_kernel<<<MROWS, 256>>>(emb, nw, nh, nl);
    // 2) QKV projection
    gemm_f16_kernel<<<dim3(QKVN/128, MROWS/128), 256, GEMM_SMEM>>>(
        nh, nl, wqh, wql, nullptr, qkv, QKVN);
    // 3) prep: RoPE + splits; V transpose
    prep_qk_kernel<<<(2*MROWS*NH*32)/256, 256>>>(qkv, cosb, sinb, qh, ql, kh, kl);
    prep_v_kernel<<<dim3(SEQ/64, NH, BATCH), 256>>>(qkv, vth, vtl);
    // 4) tensor-core causal attention
    flash_mma_kernel<<<dim3(SEQ/QROWS, NH, BATCH), 256, FLASH_SMEM>>>(
        qh, ql, kh, kl, vth, vtl, ah, al);
    // 5) out projection + residual
    gemm_f16_kernel<<<dim3(EMB/128, MROWS/128), 256, GEMM_SMEM>>>(
        ah, al, woh, wol, emb, out, EMB);
}

// round 7
// speedup vs baseline: 3.6168x; 1.0025x over previous
#include <cuda_runtime.h>
#include <cuda_fp16.h>
#include <math.h>
#include <stdint.h>

#define EMB   1024
#define NH    16
#define HD    64
#define SEQ   2048
#define BATCH 2
#define MROWS (BATCH*SEQ)     // 4096
#define QKVN  (3*EMB)         // 3072
#define EPS   1.1920929e-07f

// ---- scratch (no allocations allowed) ----
__device__ float  g_qkv[(size_t)MROWS*QKVN];
__device__ __half g_nrm_h[(size_t)MROWS*EMB];
__device__ __half g_nrm_l[(size_t)MROWS*EMB];
__device__ __half g_att_h[(size_t)MROWS*EMB];
__device__ __half g_att_l[(size_t)MROWS*EMB];
__device__ __half g_wqkv_h[(size_t)QKVN*EMB];
__device__ __half g_wqkv_l[(size_t)QKVN*EMB];
__device__ __half g_wo_h[(size_t)EMB*EMB];
__device__ __half g_wo_l[(size_t)EMB*EMB];
__device__ __half g_qh[(size_t)BATCH*NH*SEQ*HD];
__device__ __half g_ql[(size_t)BATCH*NH*SEQ*HD];
__device__ __half g_kh[(size_t)BATCH*NH*SEQ*HD];
__device__ __half g_kl[(size_t)BATCH*NH*SEQ*HD];
__device__ __half g_vth[(size_t)BATCH*NH*HD*SEQ];
__device__ __half g_vtl[(size_t)BATCH*NH*HD*SEQ];

// ============================================================
// helpers
// ============================================================
__device__ __forceinline__ uint32_t smem_u32(const void* p) {
    uint32_t a;
    asm("{ .reg .u64 t; cvta.to.shared.u64 t, %1; cvt.u32.u64 %0, t; }" : "=r"(a) : "l"(p));
    return a;
}
__device__ __forceinline__ void split_f16(float x, __half& h, __half& l) {
    h = __float2half_rn(x);
    l = __float2half_rn(x - __half2float(h));
}
__device__ __forceinline__ void mma_f16(float* c, const uint32_t* a,
                                        uint32_t b0, uint32_t b1) {
    asm volatile(
        "mma.sync.aligned.m16n8k16.row.col.f32.f16.f16.f32 "
        "{%0,%1,%2,%3}, {%4,%5,%6,%7}, {%8,%9}, {%0,%1,%2,%3};"
        : "+f"(c[0]), "+f"(c[1]), "+f"(c[2]), "+f"(c[3])
        : "r"(a[0]), "r"(a[1]), "r"(a[2]), "r"(a[3]), "r"(b0), "r"(b1));
}
__device__ __forceinline__ void cp16(uint32_t sdst, const void* gsrc) {
    asm volatile("cp.async.cg.shared.global [%0], [%1], 16;" :: "r"(sdst), "l"(gsrc));
}
#define CP_COMMIT() asm volatile("cp.async.commit_group;")
#define CP_WAIT1()  asm volatile("cp.async.wait_group 1;")
#define CP_WAIT0()  asm volatile("cp.async.wait_group 0;")

// ============================================================
// weight fp16 hi/lo split
// ============================================================
__global__ __launch_bounds__(256) void conv_f16_kernel(
    const float* __restrict__ x, __half* __restrict__ hi, __half* __restrict__ lo)
{
    int i = blockIdx.x * 256 + threadIdx.x;
    float4 v = ((const float4*)x)[i];
    __half hx, lx, hy, ly, hz, lz, hw, lw;
    split_f16(v.x, hx, lx);  split_f16(v.y, hy, ly);
    split_f16(v.z, hz, lz);  split_f16(v.w, hw, lw);
    __half2 h01 = __halves2half2(hx, hy), h23 = __halves2half2(hz, hw);
    __half2 l01 = __halves2half2(lx, ly), l23 = __halves2half2(lz, lw);
    uint2 hp, lp;
    hp.x = *(uint32_t*)&h01; hp.y = *(uint32_t*)&h23;
    lp.x = *(uint32_t*)&l01; lp.y = *(uint32_t*)&l23;
    *(uint2*)(hi + (size_t)i*4) = hp;
    *(uint2*)(lo + (size_t)i*4) = lp;
}

// ============================================================
// GEMM via mma.sync fp16 (3x hi/lo), pass-major mma ordering
// ============================================================
#define HSTRW 36
#define TW    (128*HSTRW)
#define BUFW  (4*TW)
#define GEMM_SMEM (2*BUFW*4)

__global__ __launch_bounds__(256, 1) void gemm_f16_kernel(
    const __half* __restrict__ Ah, const __half* __restrict__ Al,
    const __half* __restrict__ Bh, const __half* __restrict__ Bl,
    const float* __restrict__ Res, float* __restrict__ C, int N)
{
    extern __shared__ __align__(16) uint32_t sg[];
    uint32_t sbase = smem_u32(sg);
    int tid = threadIdx.x;
    int m0 = blockIdx.y * 128, n0 = blockIdx.x * 128;
    int lane = tid & 31, wid = tid >> 5;
    int g = lane >> 2, t4 = lane & 3;
    int wm = wid & 3, wn = wid >> 2;

    float acc[2][8][4];
    #pragma unroll
    for (int mt = 0; mt < 2; mt++)
        #pragma unroll
        for (int nt = 0; nt < 8; nt++)
            #pragma unroll
            for (int r = 0; r < 4; r++) acc[mt][nt][r] = 0.0f;

    auto issue = [&](int ch) {
        int k0 = ch * 64;
        uint32_t bufw = (uint32_t)(ch & 1) * BUFW;
        #pragma unroll
        for (int i = 0; i < 16; i++) {
            int task = tid + i * 256;
            int tile = task >> 10;
            int rem  = task & 1023;
            int row  = rem >> 3, seg = rem & 7;
            const __half* src = (tile == 0) ? Ah : (tile == 1) ? Al
                              : (tile == 2) ? Bh : Bl;
            int grow = ((tile < 2) ? m0 : n0) + row;
            uint32_t sa = sbase + (bufw + tile*TW + row*HSTRW + seg*4)*4;
            cp16(sa, src + (size_t)grow*1024 + k0 + seg*8);
        }
        CP_COMMIT();
    };

    issue(0);
    for (int ch = 0; ch < 16; ch++) {
        if (ch + 1 < 16) { issue(ch + 1); CP_WAIT1(); }
        else             { CP_WAIT0(); }
        __syncthreads();

        const uint32_t* AsH = sg + (ch & 1)*BUFW;
        const uint32_t* AsL = AsH + TW;
        const uint32_t* BsH = AsL + TW;
        const uint32_t* BsL = BsH + TW;

        #pragma unroll
        for (int s = 0; s < 4; s++) {
            uint32_t aH[2][4], aL[2][4];
            #pragma unroll
            for (int mt = 0; mt < 2; mt++) {
                int o = (wm*32 + mt*16 + g)*HSTRW + s*8 + t4;
                aH[mt][0] = AsH[o];           aH[mt][1] = AsH[o + 8*HSTRW];
                aH[mt][2] = AsH[o + 4];       aH[mt][3] = AsH[o + 8*HSTRW + 4];
                aL[mt][0] = AsL[o];           aL[mt][1] = AsL[o + 8*HSTRW];
                aL[mt][2] = AsL[o + 4];       aL[mt][3] = AsL[o + 8*HSTRW + 4];
            }
            uint32_t bh[8][2], bl[8][2];
            #pragma unroll
            for (int nt = 0; nt < 8; nt++) {
                int o = (wn*64 + nt*8 + g)*HSTRW + s*8 + t4;
                bh[nt][0] = BsH[o]; bh[nt][1] = BsH[o + 4];
                bl[nt][0] = BsL[o]; bl[nt][1] = BsL[o + 4];
            }
            // pass-major: 16 independent accs between same-acc reuses
            #pragma unroll
            for (int nt = 0; nt < 8; nt++)
                #pragma unroll
                for (int mt = 0; mt < 2; mt++)
                    mma_f16(acc[mt][nt], aH[mt], bh[nt][0], bh[nt][1]);
            #pragma unroll
            for (int nt = 0; nt < 8; nt++)
                #pragma unroll
                for (int mt = 0; mt < 2; mt++)
                    mma_f16(acc[mt][nt], aH[mt], bl[nt][0], bl[nt][1]);
            #pragma unroll
            for (int nt = 0; nt < 8; nt++)
                #pragma unroll
                for (int mt = 0; mt < 2; mt++)
                    mma_f16(acc[mt][nt], aL[mt], bh[nt][0], bh[nt][1]);
        }
        __syncthreads();
    }

    #pragma unroll
    for (int mt = 0; mt < 2; mt++) {
        int r0 = m0 + wm*32 + mt*16 + g;
        int r1 = r0 + 8;
        #pragma unroll
        for (int nt = 0; nt < 8; nt++) {
            int col = n0 + wn*64 + nt*8 + t4*2;
            float2 v0 = make_float2(acc[mt][nt][0], acc[mt][nt][1]);
            float2 v1 = make_float2(acc[mt][nt][2], acc[mt][nt][3]);
            if (Res) {
                float2 q0 = *(const float2*)(Res + (size_t)r0*N + col);
                float2 q1 = *(const float2*)(Res + (size_t)r1*N + col);
                v0.x += q0.x; v0.y += q0.y;
                v1.x += q1.x; v1.y += q1.y;
            }
            *(float2*)(C + (size_t)r0*N + col) = v0;
            *(float2*)(C + (size_t)r1*N + col) = v1;
        }
    }
}

// ============================================================
// RMSNorm -> fp16 hi/lo
// ============================================================
__global__ __launch_bounds__(256) void rmsnorm_kernel(
    const float* __restrict__ x, const float* __restrict__ w,
    __half* __restrict__ out_h, __half* __restrict__ out_l)
{
    int row = blockIdx.x;
    int tid = threadIdx.x;
    const float4* xr = (const float4*)(x + (size_t)row*EMB);
    float4 v = xr[tid];
    float ss = v.x*v.x + v.y*v.y + v.z*v.z + v.w*v.w;
    #pragma unroll
    for (int o = 16; o > 0; o >>= 1) ss += __shfl_xor_sync(0xffffffffu, ss, o);
    __shared__ float wsum[8];
    if ((tid & 31) == 0) wsum[tid >> 5] = ss;
    __syncthreads();
    if (tid < 8) {
        float t = wsum[tid];
        #pragma unroll
        for (int o = 4; o > 0; o >>= 1) t += __shfl_xor_sync(0xffu, t, o);
        if (tid == 0) wsum[0] = t;
    }
    __syncthreads();
    float inv = rsqrtf(wsum[0] * (1.0f/EMB) + EPS);
    float4 wv = ((const float4*)w)[tid];
    float4 o4;
    o4.x = v.x*inv*wv.x; o4.y = v.y*inv*wv.y;
    o4.z = v.z*inv*wv.z; o4.w = v.w*inv*wv.w;
    __half hx, lx, hy, ly, hz, lz, hw, lw;
    split_f16(o4.x, hx, lx);  split_f16(o4.y, hy, ly);
    split_f16(o4.z, hz, lz);  split_f16(o4.w, hw, lw);
    __half2 h01 = __halves2half2(hx, hy), h23 = __halves2half2(hz, hw);
    __half2 l01 = __halves2half2(lx, ly), l23 = __halves2half2(lz, lw);
    uint2 hp, lp;
    hp.x = *(uint32_t*)&h01; hp.y = *(uint32_t*)&h23;
    lp.x = *(uint32_t*)&l01; lp.y = *(uint32_t*)&l23;
    *(uint2*)(out_h + (size_t)row*EMB + tid*4) = hp;
    *(uint2*)(out_l + (size_t)row*EMB + tid*4) = lp;
}

// ============================================================
// prep_qk: RoPE + (q: scale 1/8) + fp16 split -> [bh][s][64]
// ============================================================
__global__ __launch_bounds__(256) void prep_qk_kernel(
    const float* __restrict__ qkv, const float* __restrict__ cosb,
    const float* __restrict__ sinb,
    __half* __restrict__ qh, __half* __restrict__ ql,
    __half* __restrict__ kh, __half* __restrict__ kl)
{
    int idx = blockIdx.x * blockDim.x + threadIdx.x;   // 2^22
    int d  = idx & 31;
    int h  = (idx >> 5) & 15;
    int m  = (idx >> 9) & 4095;
    int t  = idx >> 21;                 // 0=q, 1=k
    int s  = m & (SEQ - 1);
    int b  = m >> 11;
    const float* p = qkv + (size_t)m*QKVN + t*EMB + h*HD;
    float x0 = p[d], x1 = p[d + 32];
    float c0 = cosb[s*HD + d],      c1 = cosb[s*HD + d + 32];
    float s0 = sinb[s*HD + d],      s1 = sinb[s*HD + d + 32];
    float r0 = c0*x0 + s0*x1;
    float r1 = c1*x1 + s1*x0;
    if (t == 0) { r0 *= 0.125f; r1 *= 0.125f; }
    __half* oh = (t ? kh : qh);
    __half* ol = (t ? kl : ql);
    size_t base = ((size_t)(b*NH + h)*SEQ + s)*HD;
    __half h0, l0, h1, l1;
    split_f16(r0, h0, l0);
    split_f16(r1, h1, l1);
    oh[base + d]      = h0;  ol[base + d]      = l0;
    oh[base + d + 32] = h1;  ol[base + d + 32] = l1;
}

// ============================================================
// prep_v: tiled transpose V -> [bh][d][s], fp16 hi/lo
// ============================================================
__global__ __launch_bounds__(256) void prep_v_kernel(
    const float* __restrict__ qkv, __half* __restrict__ vth, __half* __restrict__ vtl)
{
    __shared__ float ts[64*65];
    int st = blockIdx.x * 64, h = blockIdx.y, b = blockIdx.z;
    int tid = threadIdx.x;
    int row = tid >> 2, seg = tid & 3;
    const float* src = qkv + (size_t)(b*SEQ + st + row)*QKVN + 2*EMB + h*HD;
    #pragma unroll
    for (int j = 0; j < 4; j++) {
        int f4 = seg*4 + j;
        float4 v = *(const float4*)(src + f4*4);
        ts[row*65 + f4*4+0] = v.x; ts[row*65 + f4*4+1] = v.y;
        ts[row*65 + f4*4+2] = v.z; ts[row*65 + f4*4+3] = v.w;
    }
    __syncthreads();
    int d = tid >> 2, ss = tid & 3;
    __half hv[16], lv[16];
    #pragma unroll
    for (int j = 0; j < 16; j++) {
        float v = ts[(ss*16 + j)*65 + d];
        split_f16(v, hv[j], lv[j]);
    }
    size_t ob = ((size_t)((b*NH + h)*HD) + d)*SEQ + st + ss*16;
    #pragma unroll
    for (int j = 0; j < 4; j++) {
        __half2 a = __halves2half2(hv[4*j], hv[4*j+1]);
        __half2 c = __halves2half2(hv[4*j+2], hv[4*j+3]);
        uint2 pk; pk.x = *(uint32_t*)&a; pk.y = *(uint32_t*)&c;
        *(uint2*)(vth + ob + 4*j) = pk;
        __half2 a2 = __halves2half2(lv[4*j], lv[4*j+1]);
        __half2 c2 = __halves2half2(lv[4*j+2], lv[4*j+3]);
        uint2 pl; pl.x = *(uint32_t*)&a2; pl.y = *(uint32_t*)&c2;
        *(uint2*)(vtl + ob + 4*j) = pl;
    }
}

// ============================================================
// Tensor-core causal flash attention (pass-major mma ordering)
// ============================================================
#define QROWS 128
#define KSTRW 36
#define QSZW  (QROWS*KSTRW)
#define KSZW  (64*KSTRW)
#define OFF_QH 0
#define OFF_QL QSZW
#define OFF_KH (2*QSZW)
#define OFF_KL (2*QSZW + 2*KSZW)
#define OFF_VH (2*QSZW + 4*KSZW)
#define OFF_VL (2*QSZW + 6*KSZW)
#define FLASH_SMEM ((2*QSZW + 8*KSZW)*4)

__global__ __launch_bounds__(256, 1) void flash_mma_kernel(
    const __half* __restrict__ Qh, const __half* __restrict__ Ql,
    const __half* __restrict__ Kh, const __half* __restrict__ Kl,
    const __half* __restrict__ Vth, const __half* __restrict__ Vtl,
    __half* __restrict__ attn_h, __half* __restrict__ attn_l)
{
    extern __shared__ __align__(16) uint32_t sf[];
    uint32_t sbase = smem_u32(sf);
    int tid = threadIdx.x, lane = tid & 31, wid = tid >> 5;
    int g = lane >> 2, t4 = lane & 3;
    int qt = (gridDim.x - 1) - blockIdx.x;
    int h = blockIdx.y, b = blockIdx.z;
    int bh = b*NH + h;
    int q0 = qt * QROWS;
    int nkt = 2*(qt + 1);

    const __half* gQh = Qh  + (size_t)bh*SEQ*HD;
    const __half* gQl = Ql  + (size_t)bh*SEQ*HD;
    const __half* gKh = Kh  + (size_t)bh*SEQ*HD;
    const __half* gKl = Kl  + (size_t)bh*SEQ*HD;
    const __half* gVh = Vth + (size_t)bh*HD*SEQ;
    const __half* gVl = Vtl + (size_t)bh*HD*SEQ;

    auto issueKV = [&](int kt) {
        int k0 = kt * 64;
        uint32_t bufw = (uint32_t)(kt & 1) * KSZW;
        #pragma unroll
        for (int i = 0; i < 4; i++) {
            int task = tid + i*256;
            int piece = task >> 9, rem = task & 511;
            int row = rem >> 3, seg = rem & 7;
            const __half* src = (piece ? gKl : gKh) + (size_t)(k0 + row)*HD + seg*8;
            uint32_t dst = sbase + (((piece ? OFF_KL : OFF_KH) + bufw) + row*KSTRW + seg*4)*4;
            cp16(dst, src);
        }
        #pragma unroll
        for (int i = 0; i < 4; i++) {
            int task = tid + i*256;
            int piece = task >> 9, rem = task & 511;
            int row = rem >> 3, seg = rem & 7;
            const __half* src = (piece ? gVl : gVh) + (size_t)row*SEQ + k0 + seg*8;
            uint32_t dst = sbase + (((piece ? OFF_VL : OFF_VH) + bufw) + row*KSTRW + seg*4)*4;
            cp16(dst, src);
        }
    };

    #pragma unroll
    for (int i = 0; i < 8; i++) {
        int task = tid + i*256;
        int piece = task >> 10, rem = task & 1023;
        int row = rem >> 3, seg = rem & 7;
        const __half* src = (piece ? gQl : gQh) + (size_t)(q0 + row)*HD + seg*8;
        uint32_t dst = sbase + ((piece ? OFF_QL : OFF_QH) + row*KSTRW + seg*4)*4;
        cp16(dst, src);
    }
    issueKV(0);
    CP_COMMIT();

    float m0 = -INFINITY, m1 = -INFINITY, l0 = 0.f, l1 = 0.f;
    float o[8][4];
    #pragma unroll
    for (int dt = 0; dt < 8; dt++)
        #pragma unroll
        for (int e = 0; e < 4; e++) o[dt][e] = 0.f;

    const uint32_t* QhS = sf + OFF_QH;
    const uint32_t* QlS = sf + OFF_QL;
    int qrow = (wid*16 + g) * KSTRW;

    for (int kt = 0; kt < nkt; kt++) {
        if (kt + 1 < nkt) { issueKV(kt + 1); CP_COMMIT(); CP_WAIT1(); }
        else              { CP_WAIT0(); }
        __syncthreads();

        uint32_t bufw = (uint32_t)(kt & 1) * KSZW;
        const uint32_t* KhS = sf + OFF_KH + bufw;
        const uint32_t* KlS = sf + OFF_KL + bufw;
        const uint32_t* VhS = sf + OFF_VH + bufw;
        const uint32_t* VlS = sf + OFF_VL + bufw;

        // ---- scores: 3x fp16, pass-major ----
        float sc[8][4];
        #pragma unroll
        for (int nt = 0; nt < 8; nt++)
            #pragma unroll
            for (int e = 0; e < 4; e++) sc[nt][e] = 0.f;

        #pragma unroll
        for (int s = 0; s < 4; s++) {
            int qo = qrow + s*8 + t4;
            uint32_t aH[4] = { QhS[qo], QhS[qo + 8*KSTRW], QhS[qo + 4], QhS[qo + 8*KSTRW + 4] };
            uint32_t aL[4] = { QlS[qo], QlS[qo + 8*KSTRW], QlS[qo + 4], QlS[qo + 8*KSTRW + 4] };
            uint32_t bh2[8][2], bl2[8][2];
            #pragma unroll
            for (int nt = 0; nt < 8; nt++) {
                int ko = (nt*8 + g)*KSTRW + s*8 + t4;
                bh2[nt][0] = KhS[ko]; bh2[nt][1] = KhS[ko + 4];
                bl2[nt][0] = KlS[ko]; bl2[nt][1] = KlS[ko + 4];
            }
            #pragma unroll
            for (int nt = 0; nt < 8; nt++)
                mma_f16(sc[nt], aH, bh2[nt][0], bh2[nt][1]);
            #pragma unroll
            for (int nt = 0; nt < 8; nt++)
                mma_f16(sc[nt], aH, bl2[nt][0], bl2[nt][1]);
            #pragma unroll
            for (int nt = 0; nt < 8; nt++)
                mma_f16(sc[nt], aL, bh2[nt][0], bh2[nt][1]);
        }

        // ---- causal mask ----
        if (kt >= 2*qt) {
            int cb = kt*64;
            int r0 = q0 + wid*16 + g, r1 = r0 + 8;
            #pragma unroll
            for (int nt = 0; nt < 8; nt++) {
                int c0 = cb + nt*8 + 2*t4;
                if (c0     > r0) sc[nt][0] = -INFINITY;
                if (c0 + 1 > r0) sc[nt][1] = -INFINITY;
                if (c0     > r1) sc[nt][2] = -INFINITY;
                if (c0 + 1 > r1) sc[nt][3] = -INFINITY;
            }
        }

        // ---- online softmax ----
        float mt0 = -INFINITY, mt1 = -INFINITY;
        #pragma unroll
        for (int nt = 0; nt < 8; nt++) {
            mt0 = fmaxf(mt0, fmaxf(sc[nt][0], sc[nt][1]));
            mt1 = fmaxf(mt1, fmaxf(sc[nt][2], sc[nt][3]));
        }
        mt0 = fmaxf(mt0, __shfl_xor_sync(0xffffffffu, mt0, 1));
        mt0 = fmaxf(mt0, __shfl_xor_sync(0xffffffffu, mt0, 2));
        mt1 = fmaxf(mt1, __shfl_xor_sync(0xffffffffu, mt1, 1));
        mt1 = fmaxf(mt1, __shfl_xor_sync(0xffffffffu, mt1, 2));
        float mn0 = fmaxf(m0, mt0), mn1 = fmaxf(m1, mt1);
        float corr0 = __expf(m0 - mn0), corr1 = __expf(m1 - mn1);
        m0 = mn0; m1 = mn1;

        float ls0 = 0.f, ls1 = 0.f;
        uint32_t phA[8], phB[8], plA[8], plB[8];
        #pragma unroll
        for (int nt = 0; nt < 8; nt++) {
            float p0 = __expf(sc[nt][0] - mn0);
            float p1 = __expf(sc[nt][1] - mn0);
            float p2 = __expf(sc[nt][2] - mn1);
            float p3 = __expf(sc[nt][3] - mn1);
            ls0 += p0 + p1;  ls1 += p2 + p3;
            __half2 hA = __floats2half2_rn(p0, p1);
            float2 fA = __half22float2(hA);
            __half2 lA = __floats2half2_rn(p0 - fA.x, p1 - fA.y);
            __half2 hB = __floats2half2_rn(p2, p3);
            float2 fB = __half22float2(hB);
            __half2 lB = __floats2half2_rn(p2 - fB.x, p3 - fB.y);
            phA[nt] = *(uint32_t*)&hA;  plA[nt] = *(uint32_t*)&lA;
            phB[nt] = *(uint32_t*)&hB;  plB[nt] = *(uint32_t*)&lB;
        }
        ls0 += __shfl_xor_sync(0xffffffffu, ls0, 1);
        ls0 += __shfl_xor_sync(0xffffffffu, ls0, 2);
        ls1 += __shfl_xor_sync(0xffffffffu, ls1, 1);
        ls1 += __shfl_xor_sync(0xffffffffu, ls1, 2);
        l0 = l0*corr0 + ls0;
        l1 = l1*corr1 + ls1;
        #pragma unroll
        for (int dt = 0; dt < 8; dt++) {
            o[dt][0] *= corr0; o[dt][1] *= corr0;
            o[dt][2] *= corr1; o[dt][3] *= corr1;
        }

        // ---- PV: 3x fp16, pass-major over dt ----
        #pragma unroll
        for (int kk = 0; kk < 4; kk++) {
            uint32_t aH[4] = { phA[2*kk], phB[2*kk], phA[2*kk+1], phB[2*kk+1] };
            uint32_t aL[4] = { plA[2*kk], plB[2*kk], plA[2*kk+1], plB[2*kk+1] };
            uint32_t vh[8][2], vl[8][2];
            #pragma unroll
            for (int dt = 0; dt < 8; dt++) {
                int vo = (dt*8 + g)*KSTRW + kk*8 + t4;
                vh[dt][0] = VhS[vo]; vh[dt][1] = VhS[vo + 4];
                vl[dt][0] = VlS[vo]; vl[dt][1] = VlS[vo + 4];
            }
            #pragma unroll
            for (int dt = 0; dt < 8; dt++)
                mma_f16(o[dt], aH, vh[dt][0], vh[dt][1]);
            #pragma unroll
            for (int dt = 0; dt < 8; dt++)
                mma_f16(o[dt], aH, vl[dt][0], vl[dt][1]);
            #pragma unroll
            for (int dt = 0; dt < 8; dt++)
                mma_f16(o[dt], aL, vh[dt][0], vh[dt][1]);
        }
        __syncthreads();
    }

    // ---- epilogue ----
    float il0 = 1.0f / l0, il1 = 1.0f / l1;
    int r0g = b*SEQ + q0 + wid*16 + g;
    int r1g = r0g + 8;
    int cbase = h*HD;
    #pragma unroll
    for (int dt = 0; dt < 8; dt++) {
        int c = cbase + dt*8 + 2*t4;
        float v0 = o[dt][0]*il0, v1 = o[dt][1]*il0;
        float v2 = o[dt][2]*il1, v3 = o[dt][3]*il1;
        __half h0,l0h,h1,l1h,h2,l2h,h3,l3h;
        split_f16(v0, h0, l0h);  split_f16(v1, h1, l1h);
        split_f16(v2, h2, l2h);  split_f16(v3, h3, l3h);
        __half2 ha = __halves2half2(h0, h1), la = __halves2half2(l0h, l1h);
        __half2 hb = __halves2half2(h2, h3), lb = __halves2half2(l2h, l3h);
        *(uint32_t*)(attn_h + (size_t)r0g*EMB + c) = *(uint32_t*)&ha;
        *(uint32_t*)(attn_l + (size_t)r0g*EMB + c) = *(uint32_t*)&la;
        *(uint32_t*)(attn_h + (size_t)r1g*EMB + c) = *(uint32_t*)&hb;
        *(uint32_t*)(attn_l + (size_t)r1g*EMB + c) = *(uint32_t*)&lb;
    }
}

// ============================================================
// launch
// ============================================================
extern "C" void kernel_launch(void* const* d_in, const int* in_sizes, int n_in,
                              void* d_out, int out_size)
{
    const float* emb  = (const float*)d_in[0];
    const float* cosb = (const float*)d_in[1];
    const float* sinb = (const float*)d_in[2];
    const float* nw   = (const float*)d_in[3];
    const float* qkvw = (const float*)d_in[4];
    const float* ow   = (const float*)d_in[5];
    float* out = (float*)d_out;

    float* qkv;
    __half *nh, *nl, *ah, *al, *wqh, *wql, *woh, *wol;
    __half *qh, *ql, *kh, *kl, *vth, *vtl;
    cudaGetSymbolAddress((void**)&qkv, g_qkv);
    cudaGetSymbolAddress((void**)&nh,  g_nrm_h);
    cudaGetSymbolAddress((void**)&nl,  g_nrm_l);
    cudaGetSymbolAddress((void**)&ah,  g_att_h);
    cudaGetSymbolAddress((void**)&al,  g_att_l);
    cudaGetSymbolAddress((void**)&wqh, g_wqkv_h);
    cudaGetSymbolAddress((void**)&wql, g_wqkv_l);
    cudaGetSymbolAddress((void**)&woh, g_wo_h);
    cudaGetSymbolAddress((void**)&wol, g_wo_l);
    cudaGetSymbolAddress((void**)&qh,  g_qh);
    cudaGetSymbolAddress((void**)&ql,  g_ql);
    cudaGetSymbolAddress((void**)&kh,  g_kh);
    cudaGetSymbolAddress((void**)&kl,  g_kl);
    cudaGetSymbolAddress((void**)&vth, g_vth);
    cudaGetSymbolAddress((void**)&vtl, g_vtl);

    cudaFuncSetAttribute(gemm_f16_kernel,
        cudaFuncAttributeMaxDynamicSharedMemorySize, GEMM_SMEM);
    cudaFuncSetAttribute(flash_mma_kernel,
        cudaFuncAttributeMaxDynamicSharedMemorySize, FLASH_SMEM);

    conv_f16_kernel<<<(QKVN*EMB/4)/256, 256>>>(qkvw, wqh, wql);
    conv_f16_kernel<<<(EMB*EMB/4)/256, 256>>>(ow, woh, wol);
    rmsnorm_kernel<<<MROWS, 256>>>(emb, nw, nh, nl);
    gemm_f16_kernel<<<dim3(QKVN/128, MROWS/128), 256, GEMM_SMEM>>>(
        nh, nl, wqh, wql, nullptr, qkv, QKVN);
    prep_qk_kernel<<<(2*MROWS*NH*32)/256, 256>>>(qkv, cosb, sinb, qh, ql, kh, kl);
    prep_v_kernel<<<dim3(SEQ/64, NH, BATCH), 256>>>(qkv, vth, vtl);
    flash_mma_kernel<<<dim3(SEQ/QROWS, NH, BATCH), 256, FLASH_SMEM>>>(
        qh, ql, kh, kl, vth, vtl, ah, al);
    gemm_f16_kernel<<<dim3(EMB/128, MROWS/128), 256, GEMM_SMEM>>>(
        ah, al, woh, wol, emb, out, EMB);
}